// round 13
// baseline (speedup 1.0000x reference)
#include <cuda_runtime.h>
#include <math.h>

#define NN 50000
#define EE 800000

__device__ float g_h[NN * 64];
__device__ float g_e[EE * 64];
__device__ float g_recv[NN * 64];
__device__ float g_hs[NN * 128];   // per-node sender-term (+ b1 + g-term)
__device__ float g_hr[NN * 128];   // per-node receiver-term
__device__ float g_c[128];         // edge: b1 + g @ w1_g
__device__ float g_cn[128];        // node: b1 + g @ w1_g

typedef unsigned long long u64;

#define FMA2(d, a, b) asm("fma.rn.f32x2 %0, %1, %2, %0;" : "+l"(d) : "l"(a), "l"(b))

__device__ __forceinline__ u64 pack_lo(float v) {
    u64 d; float z = 0.0f;
    asm("mov.b64 %0, {%1, %2};" : "=l"(d) : "f"(v), "f"(z));
    return d;
}

__device__ __forceinline__ float hadd2(u64 v) {
    float lo, hi;
    asm("mov.b64 {%0, %1}, %2;" : "=f"(lo), "=f"(hi) : "l"(v));
    return lo + hi;
}

// jax.nn.gelu (approximate=True), tanh via exp (~1e-7 accurate)
__device__ __forceinline__ float gelu_t(float x) {
    float y = 0.7978845608028654f * (x + 0.044715f * x * x * x);
    float e = __expf(2.0f * y);
    float th = 1.0f - __fdividef(2.0f, e + 1.0f);
    return 0.5f * x * (1.0f + th);
}

// ---------------------------------------------------------------------------
__global__ void embed_kernel(const float* __restrict__ nodes,
                             const float* __restrict__ w,
                             const float* __restrict__ b, int Nv) {
    int idx = blockIdx.x * blockDim.x + threadIdx.x;
    if (idx >= Nv * 64) return;
    int n = idx >> 6, j = idx & 63;
    float a = b[j];
#pragma unroll
    for (int k = 0; k < 7; k++) a += nodes[n * 7 + k] * w[k * 64 + j];
    g_h[idx] = a;
}

__global__ void zero_recv_kernel(int n) {
    int i = blockIdx.x * blockDim.x + threadIdx.x;
    if (i < n) g_recv[i] = 0.0f;
}

// c[j] = b1[j] + sum_k g[k] * w1g[k][j]  (which: 0 -> g_c, 1 -> g_cn)
__global__ void const_kernel(const float* __restrict__ gvec,
                             const float* __restrict__ w1g,
                             const float* __restrict__ b1, int gdim, int which) {
    int j = threadIdx.x;  // 128
    float a = b1[j];
    for (int k = 0; k < gdim; k++) a += gvec[k] * w1g[k * 128 + j];
    if (which) g_cn[j] = a; else g_c[j] = a;
}

// ---------------------------------------------------------------------------
// Per-node precompute: hs = h @ w1s + c ; hr = h @ w1r.  w1s/w1r are [64,128].
// 512 thr, warp = 8 nodes, grid-stride by warp.
// ---------------------------------------------------------------------------
__global__ __launch_bounds__(512, 1) void pre_kernel(
    const float* __restrict__ w1s, const float* __restrict__ w1r, int Nv) {
    constexpr int WP = 68, HB = 68, ME = 8;
    extern __shared__ float sm[];
    float* wst  = sm;               // 128*68 [j][k]
    float* wrt  = wst + 128 * WP;   // 128*68
    float* hbuf = wrt + 128 * WP;   // 16*ME*68

    int tid = threadIdx.x;
    for (int i = tid; i < 64 * 128; i += 512) {
        int k = i >> 7, j = i & 127;
        wst[j * WP + k] = w1s[i];
        wrt[j * WP + k] = w1r[i];
    }
    __syncthreads();

    int w = tid >> 5, lane = tid & 31;
    float* hb = hbuf + w * ME * HB;
    int gw = blockIdx.x * 16 + w, stride = gridDim.x * 16;
    int nTiles = (Nv + ME - 1) / ME;

    for (int tile = gw; tile < nTiles; tile += stride) {
        int nbase = tile * ME;
        for (int i = lane; i < ME * 16; i += 32) {
            int e = i >> 4, q = i & 15;
            int nid = nbase + e; if (nid >= Nv) nid = Nv - 1;
            ((float4*)(hb + e * HB))[q] = ((const float4*)g_h)[(size_t)nid * 16 + q];
        }
        __syncwarp();
        // ---- hs pass (init with c) ----
        u64 acc[4][ME];
#pragma unroll
        for (int u = 0; u < 4; u++) {
            float c = g_c[32 * u + lane];
#pragma unroll
            for (int e = 0; e < ME; e++) acc[u][e] = pack_lo(c);
        }
        {
            const float* wb = wst + lane * WP;
#pragma unroll 2
            for (int k4 = 0; k4 < 16; k4++) {
                ulonglong2 wf[4];
#pragma unroll
                for (int u = 0; u < 4; u++)
                    wf[u] = *(const ulonglong2*)(wb + u * 32 * WP + 4 * k4);
#pragma unroll
                for (int e = 0; e < ME; e++) {
                    ulonglong2 av = *(const ulonglong2*)(hb + e * HB + 4 * k4);
#pragma unroll
                    for (int u = 0; u < 4; u++) {
                        FMA2(acc[u][e], av.x, wf[u].x);
                        FMA2(acc[u][e], av.y, wf[u].y);
                    }
                }
            }
        }
#pragma unroll
        for (int e = 0; e < ME; e++) {
            int nid = nbase + e;
            if (nid < Nv)
#pragma unroll
                for (int u = 0; u < 4; u++)
                    g_hs[(size_t)nid * 128 + 32 * u + lane] = hadd2(acc[u][e]);
        }
        // ---- hr pass (init 0) ----
#pragma unroll
        for (int u = 0; u < 4; u++)
#pragma unroll
            for (int e = 0; e < ME; e++) acc[u][e] = 0ull;
        {
            const float* wb = wrt + lane * WP;
#pragma unroll 2
            for (int k4 = 0; k4 < 16; k4++) {
                ulonglong2 wf[4];
#pragma unroll
                for (int u = 0; u < 4; u++)
                    wf[u] = *(const ulonglong2*)(wb + u * 32 * WP + 4 * k4);
#pragma unroll
                for (int e = 0; e < ME; e++) {
                    ulonglong2 av = *(const ulonglong2*)(hb + e * HB + 4 * k4);
#pragma unroll
                    for (int u = 0; u < 4; u++) {
                        FMA2(acc[u][e], av.x, wf[u].x);
                        FMA2(acc[u][e], av.y, wf[u].y);
                    }
                }
            }
        }
#pragma unroll
        for (int e = 0; e < ME; e++) {
            int nid = nbase + e;
            if (nid < Nv)
#pragma unroll
                for (int u = 0; u < 4; u++)
                    g_hr[(size_t)nid * 128 + 32 * u + lane] = hadd2(acc[u][e]);
        }
        __syncwarp();
    }
}

// ---------------------------------------------------------------------------
// Edge MLP with factored layer 1: hidden = gelu(hs[s] + hr[r] + (e@w1e)).
// Warp-private tiles of 8 edges, grid-stride; NO in-loop CTA barriers.
// ---------------------------------------------------------------------------
template <bool HAS_E>
__global__ __launch_bounds__(512, 1) void edge_kernel(
    const int* __restrict__ senders, const int* __restrict__ receivers,
    const float* __restrict__ w1e, const float* __restrict__ w2,
    const float* __restrict__ b2, int En, int write_e) {
    constexpr int W1P = 68, EBP = 68, HP = 132, W2P = 132, ME = 8;
    extern __shared__ float sm[];
    float* w2t  = sm;                              // 64*132 [j][k] k<128
    float* b2s  = w2t + 64 * W2P;                  // 64
    float* w1t  = b2s + 64;                        // HAS_E: 128*68 [j][k] k<64
    float* ebuf = w1t + (HAS_E ? 128 * W1P : 0);   // HAS_E: 16*ME*68
    float* hid  = ebuf + (HAS_E ? 16 * ME * EBP : 0); // 16*ME*132

    int tid = threadIdx.x;
    for (int i = tid; i < 128 * 64; i += 512) {
        int k = i >> 6, j = i & 63;
        w2t[j * W2P + k] = w2[i];
    }
    if (HAS_E)
        for (int i = tid; i < 64 * 128; i += 512) {
            int k = i >> 7, j = i & 127;
            w1t[j * W1P + k] = w1e[i];
        }
    if (tid < 64) b2s[tid] = b2[tid];
    __syncthreads();

    int w = tid >> 5, lane = tid & 31;
    float* eb = ebuf + w * ME * EBP;
    float* hidw = hid + w * ME * HP;
    int gw = blockIdx.x * 16 + w, stride = gridDim.x * 16;
    int nTiles = (En + ME - 1) / ME;

    for (int tile = gw; tile < nTiles; tile += stride) {
        int ebase = tile * ME;
        int se[ME], re[ME];
#pragma unroll
        for (int e = 0; e < ME; e++) {
            int eid = ebase + e; if (eid >= En) eid = En - 1;
            se[e] = senders[eid];
            re[e] = receivers[eid];
        }
        if (HAS_E) {
            for (int i = lane; i < ME * 16; i += 32) {
                int e = i >> 4, q = i & 15;
                int eid = ebase + e; if (eid >= En) eid = En - 1;
                ((float4*)(eb + e * EBP))[q] = ((const float4*)g_e)[(size_t)eid * 16 + q];
            }
            __syncwarp();
        }
        // ---- layer 1: init from hs/hr gathers, then optional e@w1e ----
        u64 acc[4][ME];
#pragma unroll
        for (int u = 0; u < 4; u++) {
            int j = 32 * u + lane;
#pragma unroll
            for (int e = 0; e < ME; e++) {
                float v = g_hs[(size_t)se[e] * 128 + j] + g_hr[(size_t)re[e] * 128 + j];
                acc[u][e] = pack_lo(v);
            }
        }
        if (HAS_E) {
            const float* wb = w1t + lane * W1P;
#pragma unroll 2
            for (int k4 = 0; k4 < 16; k4++) {
                ulonglong2 wf[4];
#pragma unroll
                for (int u = 0; u < 4; u++)
                    wf[u] = *(const ulonglong2*)(wb + u * 32 * W1P + 4 * k4);
#pragma unroll
                for (int e = 0; e < ME; e++) {
                    ulonglong2 av = *(const ulonglong2*)(eb + e * EBP + 4 * k4);
#pragma unroll
                    for (int u = 0; u < 4; u++) {
                        FMA2(acc[u][e], av.x, wf[u].x);
                        FMA2(acc[u][e], av.y, wf[u].y);
                    }
                }
            }
        }
        // ---- gelu into own-warp smem rows ----
#pragma unroll
        for (int e = 0; e < ME; e++)
#pragma unroll
            for (int u = 0; u < 4; u++) {
                int j = 32 * u + lane;
                hidw[e * HP + j] = gelu_t(hadd2(acc[u][e]));
            }
        __syncwarp();
        // ---- layer 2 ----
        u64 o0[ME], o1[ME];
#pragma unroll
        for (int e = 0; e < ME; e++) { o0[e] = 0ull; o1[e] = 0ull; }
        {
            const float* wa = w2t + lane * W2P;
            const float* wbp = w2t + (lane + 32) * W2P;
#pragma unroll 2
            for (int k4 = 0; k4 < 32; k4++) {
                ulonglong2 va = *(const ulonglong2*)(wa + 4 * k4);
                ulonglong2 vb = *(const ulonglong2*)(wbp + 4 * k4);
#pragma unroll
                for (int e = 0; e < ME; e++) {
                    ulonglong2 av = *(const ulonglong2*)(hidw + e * HP + 4 * k4);
                    FMA2(o0[e], av.x, va.x);
                    FMA2(o0[e], av.y, va.y);
                    FMA2(o1[e], av.x, vb.x);
                    FMA2(o1[e], av.y, vb.y);
                }
            }
        }
        // ---- scatter ----
#pragma unroll
        for (int e = 0; e < ME; e++) {
            int eid = ebase + e;
            if (eid < En) {
                float u0 = hadd2(o0[e]) + b2s[lane];
                float u1 = hadd2(o1[e]) + b2s[lane + 32];
                if (write_e) {
                    g_e[(size_t)eid * 64 + lane] = u0;
                    g_e[(size_t)eid * 64 + 32 + lane] = u1;
                }
                atomicAdd(&g_recv[(size_t)re[e] * 64 + lane], u0);
                atomicAdd(&g_recv[(size_t)re[e] * 64 + 32 + lane], u1);
            }
        }
        __syncwarp();
    }
}

// ---------------------------------------------------------------------------
// Fused node MLP + residual + LayerNorm. g-term folded (k=128), warp = 8.
// ---------------------------------------------------------------------------
__global__ __launch_bounds__(512, 1) void node_kernel(
    const float* __restrict__ w1, const float* __restrict__ w2,
    const float* __restrict__ b2,
    const float* __restrict__ lnsc, const float* __restrict__ lnbi, int Nv) {
    constexpr int INP = 132, W1P = 132, W2P = 132, MB = 128, NT = 512, ME = 8;
    extern __shared__ float sm[];
    float* w1t = sm;                  // 128*132 [j][k] k<128
    float* w2t = w1t + 128 * W1P;     // 64*132
    float* b2s = w2t + 64 * W2P;      // 64
    float* lns = b2s + 64;            // 64
    float* lnb = lns + 64;            // 64
    float* inb = lnb + 64;            // MB*132 ; rows double as hid

    int tid = threadIdx.x;
    for (int i = tid; i < 128 * 128; i += NT) {
        int k = i >> 7, j = i & 127;
        w1t[j * W1P + k] = w1[i];
    }
    for (int i = tid; i < 128 * 64; i += NT) {
        int k = i >> 6, j = i & 63;
        w2t[j * W2P + k] = w2[i];
    }
    if (tid < 64) b2s[tid] = b2[tid];
    else if (tid < 128) lns[tid - 64] = lnsc[tid - 64];
    else if (tid < 192) lnb[tid - 128] = lnbi[tid - 128];
    __syncthreads();

    int w = tid >> 5, lane = tid & 31;
    float cn[4];
#pragma unroll
    for (int u = 0; u < 4; u++) cn[u] = g_cn[32 * u + lane];

    int nIter = (Nv + MB - 1) / MB;
    for (int it = blockIdx.x; it < nIter; it += gridDim.x) {
        int nbase = it * MB;
        // ---- gather [h | recv] ----
        {
            const float4* hp = (const float4*)g_h;
            const float4* rp = (const float4*)g_recv;
            for (int c = tid; c < MB * 32; c += NT) {
                int m = c >> 5, q = c & 31;
                int nid = nbase + m; if (nid >= Nv) nid = Nv - 1;
                float4 v = (q < 16) ? hp[(size_t)nid * 16 + q]
                                    : rp[(size_t)nid * 16 + (q - 16)];
                ((float4*)(inb + m * INP))[q] = v;
            }
        }
        __syncthreads();
        // ---- layer 1 ----
        u64 acc[4][ME];
#pragma unroll
        for (int u = 0; u < 4; u++)
#pragma unroll
            for (int e = 0; e < ME; e++) acc[u][e] = pack_lo(cn[u]);
        {
            const float* inw = inb + (w * ME) * INP;
            const float* wb = w1t + lane * W1P;
#pragma unroll 2
            for (int k4 = 0; k4 < 32; k4++) {
                ulonglong2 wf[4];
#pragma unroll
                for (int u = 0; u < 4; u++)
                    wf[u] = *(const ulonglong2*)(wb + u * 32 * W1P + 4 * k4);
#pragma unroll
                for (int e = 0; e < ME; e++) {
                    ulonglong2 av = *(const ulonglong2*)(inw + e * INP + 4 * k4);
#pragma unroll
                    for (int u = 0; u < 4; u++) {
                        FMA2(acc[u][e], av.x, wf[u].x);
                        FMA2(acc[u][e], av.y, wf[u].y);
                    }
                }
            }
        }
        // ---- gelu into own rows of inb ----
        {
            float* hidw = inb + (w * ME) * INP;
#pragma unroll
            for (int e = 0; e < ME; e++)
#pragma unroll
                for (int u = 0; u < 4; u++) {
                    int j = 32 * u + lane;
                    hidw[e * INP + j] = gelu_t(hadd2(acc[u][e]));
                }
        }
        __syncwarp();
        // ---- layer 2 ----
        u64 o0[ME], o1[ME];
#pragma unroll
        for (int e = 0; e < ME; e++) { o0[e] = 0ull; o1[e] = 0ull; }
        {
            const float* hw = inb + (w * ME) * INP;
            const float* wa = w2t + lane * W2P;
            const float* wbp = w2t + (lane + 32) * W2P;
#pragma unroll 2
            for (int k4 = 0; k4 < 32; k4++) {
                ulonglong2 va = *(const ulonglong2*)(wa + 4 * k4);
                ulonglong2 vb = *(const ulonglong2*)(wbp + 4 * k4);
#pragma unroll
                for (int e = 0; e < ME; e++) {
                    ulonglong2 av = *(const ulonglong2*)(hw + e * INP + 4 * k4);
                    FMA2(o0[e], av.x, va.x);
                    FMA2(o0[e], av.y, va.y);
                    FMA2(o1[e], av.x, vb.x);
                    FMA2(o1[e], av.y, vb.y);
                }
            }
        }
        // ---- residual + LayerNorm ----
#pragma unroll
        for (int e = 0; e < ME; e++) {
            int nid = nbase + w * ME + e;
            int nc = nid < Nv ? nid : Nv - 1;
            float h0 = g_h[(size_t)nc * 64 + lane];
            float h1 = g_h[(size_t)nc * 64 + 32 + lane];
            float x0 = h0 + hadd2(o0[e]) + b2s[lane];
            float x1 = h1 + hadd2(o1[e]) + b2s[lane + 32];
            float s = x0 + x1, q = x0 * x0 + x1 * x1;
#pragma unroll
            for (int d = 16; d; d >>= 1) {
                s += __shfl_xor_sync(0xffffffffu, s, d);
                q += __shfl_xor_sync(0xffffffffu, q, d);
            }
            float mu = s * (1.0f / 64.0f);
            float var = q * (1.0f / 64.0f) - mu * mu;
            float inv = rsqrtf(var + 1e-6f);
            if (nid < Nv) {
                g_h[(size_t)nid * 64 + lane]      = (x0 - mu) * inv * lns[lane] + lnb[lane];
                g_h[(size_t)nid * 64 + 32 + lane] = (x1 - mu) * inv * lns[lane + 32] + lnb[lane + 32];
            }
        }
        __syncthreads();
    }
}

// ---------------------------------------------------------------------------
__global__ void decode_kernel(const float* __restrict__ dec_w,
                              const float* __restrict__ dec_b,
                              float* __restrict__ out, int Nv) {
    int gwarp = (blockIdx.x * blockDim.x + threadIdx.x) >> 5;
    int lane = threadIdx.x & 31;
    int nWarps = (gridDim.x * blockDim.x) >> 5;
    for (int n = gwarp; n < Nv; n += nWarps) {
        float h0 = g_h[n * 64 + lane];
        float h1 = g_h[n * 64 + 32 + lane];
        float p[7];
#pragma unroll
        for (int k = 0; k < 7; k++)
            p[k] = h0 * dec_w[lane * 7 + k] + h1 * dec_w[(lane + 32) * 7 + k];
#pragma unroll
        for (int k = 0; k < 7; k++)
#pragma unroll
            for (int d = 16; d; d >>= 1) p[k] += __shfl_xor_sync(0xffffffffu, p[k], d);
        if (lane < 7) out[n * 7 + lane] = p[lane] + dec_b[lane];
    }
}

// ---------------------------------------------------------------------------
extern "C" void kernel_launch(void* const* d_in, const int* in_sizes, int n_in,
                              void* d_out, int out_size) {
    const float* nodes   = (const float*)d_in[0];
    const int*   senders = (const int*)d_in[1];
    const int*   recvrs  = (const int*)d_in[2];
    const float* g       = (const float*)d_in[3];
    const float* embed_w = (const float*)d_in[4];
    const float* embed_b = (const float*)d_in[5];
    const float* ew1f    = (const float*)d_in[6];
    const float* ew1r    = (const float*)d_in[7];
    const float* eb1     = (const float*)d_in[8];
    const float* ew2     = (const float*)d_in[9];
    const float* eb2     = (const float*)d_in[10];
    const float* nw1     = (const float*)d_in[11];
    const float* nb1     = (const float*)d_in[12];
    const float* nw2     = (const float*)d_in[13];
    const float* nb2     = (const float*)d_in[14];
    const float* lnsc    = (const float*)d_in[15];
    const float* lnbi    = (const float*)d_in[16];
    const float* dec_w   = (const float*)d_in[17];
    const float* dec_b   = (const float*)d_in[18];
    float* out = (float*)d_out;

    int En = in_sizes[1];
    int Nv = in_sizes[0] / 7;

    size_t sm_pre = (size_t)(128 * 68 * 2 + 16 * 8 * 68) * 4;
    size_t sm_e0  = (size_t)(64 * 132 + 64 + 16 * 8 * 132) * 4;
    size_t sm_e1  = (size_t)(64 * 132 + 64 + 128 * 68 + 16 * 8 * 68 + 16 * 8 * 132) * 4;
    size_t sm_n   = (size_t)(128 * 132 + 64 * 132 + 64 + 64 + 64 + 128 * 132) * 4;

    cudaFuncSetAttribute(pre_kernel,
                         cudaFuncAttributeMaxDynamicSharedMemorySize, (int)sm_pre);
    cudaFuncSetAttribute(edge_kernel<false>,
                         cudaFuncAttributeMaxDynamicSharedMemorySize, (int)sm_e0);
    cudaFuncSetAttribute(edge_kernel<true>,
                         cudaFuncAttributeMaxDynamicSharedMemorySize, (int)sm_e1);
    cudaFuncSetAttribute(node_kernel,
                         cudaFuncAttributeMaxDynamicSharedMemorySize, (int)sm_n);

    const int GRID = 148;
    const int GRID_N = 131;

    embed_kernel<<<(Nv * 64 + 255) / 256, 256>>>(nodes, embed_w, embed_b, Nv);

    for (int t = 0; t < 3; t++) {
        zero_recv_kernel<<<(Nv * 64 + 255) / 256, 256>>>(Nv * 64);
        if (t == 0) {
            // w1f rows: [0:64)=s, [64:128)=r, [128:144)=g
            const_kernel<<<1, 128>>>(g, ew1f + 128 * 128, eb1, 16, 0);
            pre_kernel<<<GRID, 512, sm_pre>>>(ew1f, ew1f + 64 * 128, Nv);
            edge_kernel<false><<<GRID, 512, sm_e0>>>(
                senders, recvrs, nullptr, ew2, eb2, En, 1);
        } else {
            // w1rest[t-1] rows: [0:64)=e, [64:128)=s, [128:192)=r, [192:208)=g
            const float* base = ew1r + (size_t)(t - 1) * 208 * 128;
            const_kernel<<<1, 128>>>(g, base + 192 * 128, eb1 + t * 128, 16, 0);
            pre_kernel<<<GRID, 512, sm_pre>>>(base + 64 * 128, base + 128 * 128, Nv);
            edge_kernel<true><<<GRID, 512, sm_e1>>>(
                senders, recvrs, base,
                ew2 + (size_t)t * 128 * 64, eb2 + t * 64, En, (t == 2) ? 0 : 1);
        }
        // node: w1 rows [0:64)=h, [64:128)=recv, [128:144)=g (folded into g_cn)
        const float* nbase = nw1 + (size_t)t * 144 * 128;
        const_kernel<<<1, 128>>>(g, nbase + 128 * 128, nb1 + t * 128, 16, 1);
        node_kernel<<<GRID_N, 512, sm_n>>>(
            nbase, nw2 + (size_t)t * 128 * 64, nb2 + t * 64,
            lnsc + t * 64, lnbi + t * 64, Nv);
    }

    decode_kernel<<<208, 256>>>(dec_w, dec_b, out, Nv);
}

// round 14
// speedup vs baseline: 1.0416x; 1.0416x over previous
#include <cuda_runtime.h>
#include <math.h>

#define NN 50000
#define EE 800000

__device__ float g_h[NN * 64];
__device__ float g_e[EE * 64];
__device__ float g_recv[NN * 64];
__device__ float g_hs[NN * 128];   // per-node sender-term (+ b1 + g-term)
__device__ float g_hr[NN * 128];   // per-node receiver-term
__device__ float g_c[128];         // edge: b1 + g @ w1_g
__device__ float g_cn[128];        // node: b1 + g @ w1_g

typedef unsigned long long u64;

#define FMA2(d, a, b) asm("fma.rn.f32x2 %0, %1, %2, %0;" : "+l"(d) : "l"(a), "l"(b))

__device__ __forceinline__ u64 pack_lo(float v) {
    u64 d; float z = 0.0f;
    asm("mov.b64 %0, {%1, %2};" : "=l"(d) : "f"(v), "f"(z));
    return d;
}

__device__ __forceinline__ float hadd2(u64 v) {
    float lo, hi;
    asm("mov.b64 {%0, %1}, %2;" : "=f"(lo), "=f"(hi) : "l"(v));
    return lo + hi;
}

// jax.nn.gelu (approximate=True), tanh via exp (~1e-7 accurate)
__device__ __forceinline__ float gelu_t(float x) {
    float y = 0.7978845608028654f * (x + 0.044715f * x * x * x);
    float e = __expf(2.0f * y);
    float th = 1.0f - __fdividef(2.0f, e + 1.0f);
    return 0.5f * x * (1.0f + th);
}

// ---------------------------------------------------------------------------
__global__ void embed_kernel(const float* __restrict__ nodes,
                             const float* __restrict__ w,
                             const float* __restrict__ b, int Nv) {
    int idx = blockIdx.x * blockDim.x + threadIdx.x;
    if (idx >= Nv * 64) return;
    int n = idx >> 6, j = idx & 63;
    float a = b[j];
#pragma unroll
    for (int k = 0; k < 7; k++) a += nodes[n * 7 + k] * w[k * 64 + j];
    g_h[idx] = a;
}

__global__ void zero_recv_kernel(int n) {
    int i = blockIdx.x * blockDim.x + threadIdx.x;
    if (i < n) g_recv[i] = 0.0f;
}

// c[j] = b1[j] + sum_k g[k] * w1g[k][j]  (which: 0 -> g_c, 1 -> g_cn)
__global__ void const_kernel(const float* __restrict__ gvec,
                             const float* __restrict__ w1g,
                             const float* __restrict__ b1, int gdim, int which) {
    int j = threadIdx.x;  // 128
    float a = b1[j];
    for (int k = 0; k < gdim; k++) a += gvec[k] * w1g[k * 128 + j];
    if (which) g_cn[j] = a; else g_c[j] = a;
}

// ---------------------------------------------------------------------------
// Per-node precompute: hs = h @ w1s + c ; hr = h @ w1r.  w1s/w1r are [64,128].
// 512 thr, warp = 6 nodes, grid-stride by warp.  (R12 structure)
// ---------------------------------------------------------------------------
__global__ __launch_bounds__(512, 1) void pre_kernel(
    const float* __restrict__ w1s, const float* __restrict__ w1r, int Nv) {
    constexpr int WP = 68, HB = 68;
    extern __shared__ float sm[];
    float* wst  = sm;               // 128*68 [j][k]
    float* wrt  = wst + 128 * WP;   // 128*68
    float* hbuf = wrt + 128 * WP;   // 16*6*68

    int tid = threadIdx.x;
    for (int i = tid; i < 64 * 128; i += 512) {
        int k = i >> 7, j = i & 127;
        wst[j * WP + k] = w1s[i];
        wrt[j * WP + k] = w1r[i];
    }
    __syncthreads();

    int w = tid >> 5, lane = tid & 31;
    float* hb = hbuf + w * 6 * HB;
    int gw = blockIdx.x * 16 + w, stride = gridDim.x * 16;
    int nTiles = (Nv + 5) / 6;

    for (int tile = gw; tile < nTiles; tile += stride) {
        int nbase = tile * 6;
        for (int i = lane; i < 96; i += 32) {
            int e = i >> 4, q = i & 15;
            int nid = nbase + e; if (nid >= Nv) nid = Nv - 1;
            ((float4*)(hb + e * HB))[q] = ((const float4*)g_h)[(size_t)nid * 16 + q];
        }
        __syncwarp();
        // ---- hs pass (init with c) ----
        u64 acc[4][6];
#pragma unroll
        for (int u = 0; u < 4; u++) {
            float c = g_c[32 * u + lane];
#pragma unroll
            for (int e = 0; e < 6; e++) acc[u][e] = pack_lo(c);
        }
        {
            const float* wb = wst + lane * WP;
#pragma unroll 2
            for (int k4 = 0; k4 < 16; k4++) {
                ulonglong2 wf[4];
#pragma unroll
                for (int u = 0; u < 4; u++)
                    wf[u] = *(const ulonglong2*)(wb + u * 32 * WP + 4 * k4);
#pragma unroll
                for (int e = 0; e < 6; e++) {
                    ulonglong2 av = *(const ulonglong2*)(hb + e * HB + 4 * k4);
#pragma unroll
                    for (int u = 0; u < 4; u++) {
                        FMA2(acc[u][e], av.x, wf[u].x);
                        FMA2(acc[u][e], av.y, wf[u].y);
                    }
                }
            }
        }
#pragma unroll
        for (int e = 0; e < 6; e++) {
            int nid = nbase + e;
            if (nid < Nv)
#pragma unroll
                for (int u = 0; u < 4; u++)
                    g_hs[(size_t)nid * 128 + 32 * u + lane] = hadd2(acc[u][e]);
        }
        // ---- hr pass (init 0) ----
#pragma unroll
        for (int u = 0; u < 4; u++)
#pragma unroll
            for (int e = 0; e < 6; e++) acc[u][e] = 0ull;
        {
            const float* wb = wrt + lane * WP;
#pragma unroll 2
            for (int k4 = 0; k4 < 16; k4++) {
                ulonglong2 wf[4];
#pragma unroll
                for (int u = 0; u < 4; u++)
                    wf[u] = *(const ulonglong2*)(wb + u * 32 * WP + 4 * k4);
#pragma unroll
                for (int e = 0; e < 6; e++) {
                    ulonglong2 av = *(const ulonglong2*)(hb + e * HB + 4 * k4);
#pragma unroll
                    for (int u = 0; u < 4; u++) {
                        FMA2(acc[u][e], av.x, wf[u].x);
                        FMA2(acc[u][e], av.y, wf[u].y);
                    }
                }
            }
        }
#pragma unroll
        for (int e = 0; e < 6; e++) {
            int nid = nbase + e;
            if (nid < Nv)
#pragma unroll
                for (int u = 0; u < 4; u++)
                    g_hr[(size_t)nid * 128 + 32 * u + lane] = hadd2(acc[u][e]);
        }
        __syncwarp();
    }
}

// ---------------------------------------------------------------------------
// Edge MLP with factored layer 1: hidden = gelu(hs[s] + hr[r] + (e@w1e)).
// Warp-private tiles of 6 edges, grid-stride; NO in-loop CTA barriers.
// ---------------------------------------------------------------------------
template <bool HAS_E>
__global__ __launch_bounds__(512, 1) void edge_kernel(
    const int* __restrict__ senders, const int* __restrict__ receivers,
    const float* __restrict__ w1e, const float* __restrict__ w2,
    const float* __restrict__ b2, int En, int write_e) {
    constexpr int W1P = 68, EBP = 68, HP = 132, W2P = 132;
    extern __shared__ float sm[];
    float* w2t  = sm;                              // 64*132 [j][k] k<128
    float* b2s  = w2t + 64 * W2P;                  // 64
    float* w1t  = b2s + 64;                        // HAS_E: 128*68 [j][k] k<64
    float* ebuf = w1t + (HAS_E ? 128 * W1P : 0);   // HAS_E: 16*6*68
    float* hid  = ebuf + (HAS_E ? 16 * 6 * EBP : 0); // 16*6*132

    int tid = threadIdx.x;
    for (int i = tid; i < 128 * 64; i += 512) {
        int k = i >> 6, j = i & 63;
        w2t[j * W2P + k] = w2[i];
    }
    if (HAS_E)
        for (int i = tid; i < 64 * 128; i += 512) {
            int k = i >> 7, j = i & 127;
            w1t[j * W1P + k] = w1e[i];
        }
    if (tid < 64) b2s[tid] = b2[tid];
    __syncthreads();

    int w = tid >> 5, lane = tid & 31;
    float* eb = ebuf + w * 6 * EBP;
    float* hidw = hid + w * 6 * HP;
    int gw = blockIdx.x * 16 + w, stride = gridDim.x * 16;
    int nTiles = (En + 5) / 6;

    for (int tile = gw; tile < nTiles; tile += stride) {
        int ebase = tile * 6;
        int se[6], re[6];
#pragma unroll
        for (int e = 0; e < 6; e++) {
            int eid = ebase + e; if (eid >= En) eid = En - 1;
            se[e] = senders[eid];
            re[e] = receivers[eid];
        }
        if (HAS_E) {
            for (int i = lane; i < 96; i += 32) {
                int e = i >> 4, q = i & 15;
                int eid = ebase + e; if (eid >= En) eid = En - 1;
                ((float4*)(eb + e * EBP))[q] = ((const float4*)g_e)[(size_t)eid * 16 + q];
            }
            __syncwarp();
        }
        // ---- layer 1: init from hs/hr gathers, then optional e@w1e ----
        u64 acc[4][6];
#pragma unroll
        for (int u = 0; u < 4; u++) {
            int j = 32 * u + lane;
#pragma unroll
            for (int e = 0; e < 6; e++) {
                float v = g_hs[(size_t)se[e] * 128 + j] + g_hr[(size_t)re[e] * 128 + j];
                acc[u][e] = pack_lo(v);
            }
        }
        if (HAS_E) {
            const float* wb = w1t + lane * W1P;
#pragma unroll 2
            for (int k4 = 0; k4 < 16; k4++) {
                ulonglong2 wf[4];
#pragma unroll
                for (int u = 0; u < 4; u++)
                    wf[u] = *(const ulonglong2*)(wb + u * 32 * W1P + 4 * k4);
#pragma unroll
                for (int e = 0; e < 6; e++) {
                    ulonglong2 av = *(const ulonglong2*)(eb + e * EBP + 4 * k4);
#pragma unroll
                    for (int u = 0; u < 4; u++) {
                        FMA2(acc[u][e], av.x, wf[u].x);
                        FMA2(acc[u][e], av.y, wf[u].y);
                    }
                }
            }
        }
        // ---- gelu into own-warp smem rows ----
#pragma unroll
        for (int e = 0; e < 6; e++)
#pragma unroll
            for (int u = 0; u < 4; u++) {
                int j = 32 * u + lane;
                hidw[e * HP + j] = gelu_t(hadd2(acc[u][e]));
            }
        __syncwarp();
        // ---- layer 2 ----
        u64 o0[6], o1[6];
#pragma unroll
        for (int e = 0; e < 6; e++) { o0[e] = 0ull; o1[e] = 0ull; }
        {
            const float* wa = w2t + lane * W2P;
            const float* wbp = w2t + (lane + 32) * W2P;
#pragma unroll 2
            for (int k4 = 0; k4 < 32; k4++) {
                ulonglong2 va = *(const ulonglong2*)(wa + 4 * k4);
                ulonglong2 vb = *(const ulonglong2*)(wbp + 4 * k4);
#pragma unroll
                for (int e = 0; e < 6; e++) {
                    ulonglong2 av = *(const ulonglong2*)(hidw + e * HP + 4 * k4);
                    FMA2(o0[e], av.x, va.x);
                    FMA2(o0[e], av.y, va.y);
                    FMA2(o1[e], av.x, vb.x);
                    FMA2(o1[e], av.y, vb.y);
                }
            }
        }
        // ---- scatter ----
#pragma unroll
        for (int e = 0; e < 6; e++) {
            int eid = ebase + e;
            if (eid < En) {
                float u0 = hadd2(o0[e]) + b2s[lane];
                float u1 = hadd2(o1[e]) + b2s[lane + 32];
                if (write_e) {
                    g_e[(size_t)eid * 64 + lane] = u0;
                    g_e[(size_t)eid * 64 + 32 + lane] = u1;
                }
                atomicAdd(&g_recv[(size_t)re[e] * 64 + lane], u0);
                atomicAdd(&g_recv[(size_t)re[e] * 64 + 32 + lane], u1);
            }
        }
        __syncwarp();
    }
}

// ---------------------------------------------------------------------------
// Fused node MLP + residual + LayerNorm. g-term folded into g_cn (k=128).
// Gather phase re-zeros g_recv for the next step (single reader per chunk).
// ---------------------------------------------------------------------------
__global__ __launch_bounds__(512, 1) void node_kernel(
    const float* __restrict__ w1, const float* __restrict__ w2,
    const float* __restrict__ b2,
    const float* __restrict__ lnsc, const float* __restrict__ lnbi, int Nv) {
    constexpr int INP = 132, W1P = 132, W2P = 132, MB = 96, NT = 512;
    extern __shared__ float sm[];
    float* w1t = sm;                  // 128*132 [j][k] k<128
    float* w2t = w1t + 128 * W1P;     // 64*132
    float* b2s = w2t + 64 * W2P;      // 64
    float* lns = b2s + 64;            // 64
    float* lnb = lns + 64;            // 64
    float* inb = lnb + 64;            // MB*132 ; rows double as hid

    int tid = threadIdx.x;
    for (int i = tid; i < 128 * 128; i += NT) {
        int k = i >> 7, j = i & 127;
        w1t[j * W1P + k] = w1[i];
    }
    for (int i = tid; i < 128 * 64; i += NT) {
        int k = i >> 6, j = i & 63;
        w2t[j * W2P + k] = w2[i];
    }
    if (tid < 64) b2s[tid] = b2[tid];
    else if (tid < 128) lns[tid - 64] = lnsc[tid - 64];
    else if (tid < 192) lnb[tid - 128] = lnbi[tid - 128];
    __syncthreads();

    int w = tid >> 5, lane = tid & 31;
    float cn[4];
#pragma unroll
    for (int u = 0; u < 4; u++) cn[u] = g_cn[32 * u + lane];

    int nIter = (Nv + MB - 1) / MB;
    for (int it = blockIdx.x; it < nIter; it += gridDim.x) {
        int nbase = it * MB;
        // ---- gather [h | recv]; zero recv after its single read ----
        {
            const float4* hp = (const float4*)g_h;
            float4* rp = (float4*)g_recv;
            for (int c = tid; c < MB * 32; c += NT) {
                int m = c >> 5, q = c & 31;
                int nid = nbase + m;
                int ncl = nid < Nv ? nid : Nv - 1;
                float4 v;
                if (q < 16) {
                    v = hp[(size_t)ncl * 16 + q];
                } else {
                    v = rp[(size_t)ncl * 16 + (q - 16)];
                    if (nid < Nv)
                        rp[(size_t)nid * 16 + (q - 16)] =
                            make_float4(0.f, 0.f, 0.f, 0.f);
                }
                ((float4*)(inb + m * INP))[q] = v;
            }
        }
        __syncthreads();
        // ---- layer 1 ----
        u64 acc[4][6];
#pragma unroll
        for (int u = 0; u < 4; u++)
#pragma unroll
            for (int e = 0; e < 6; e++) acc[u][e] = pack_lo(cn[u]);
        {
            const float* inw = inb + (w * 6) * INP;
            const float* wb = w1t + lane * W1P;
#pragma unroll 2
            for (int k4 = 0; k4 < 32; k4++) {
                ulonglong2 wf[4];
#pragma unroll
                for (int u = 0; u < 4; u++)
                    wf[u] = *(const ulonglong2*)(wb + u * 32 * W1P + 4 * k4);
#pragma unroll
                for (int e = 0; e < 6; e++) {
                    ulonglong2 av = *(const ulonglong2*)(inw + e * INP + 4 * k4);
#pragma unroll
                    for (int u = 0; u < 4; u++) {
                        FMA2(acc[u][e], av.x, wf[u].x);
                        FMA2(acc[u][e], av.y, wf[u].y);
                    }
                }
            }
        }
        // ---- gelu into own rows of inb ----
        {
            float* hidw = inb + (w * 6) * INP;
#pragma unroll
            for (int e = 0; e < 6; e++)
#pragma unroll
                for (int u = 0; u < 4; u++) {
                    int j = 32 * u + lane;
                    hidw[e * INP + j] = gelu_t(hadd2(acc[u][e]));
                }
        }
        __syncwarp();
        // ---- layer 2 ----
        u64 o0[6], o1[6];
#pragma unroll
        for (int e = 0; e < 6; e++) { o0[e] = 0ull; o1[e] = 0ull; }
        {
            const float* hw = inb + (w * 6) * INP;
            const float* wa = w2t + lane * W2P;
            const float* wbp = w2t + (lane + 32) * W2P;
#pragma unroll 2
            for (int k4 = 0; k4 < 32; k4++) {
                ulonglong2 va = *(const ulonglong2*)(wa + 4 * k4);
                ulonglong2 vb = *(const ulonglong2*)(wbp + 4 * k4);
#pragma unroll
                for (int e = 0; e < 6; e++) {
                    ulonglong2 av = *(const ulonglong2*)(hw + e * INP + 4 * k4);
                    FMA2(o0[e], av.x, va.x);
                    FMA2(o0[e], av.y, va.y);
                    FMA2(o1[e], av.x, vb.x);
                    FMA2(o1[e], av.y, vb.y);
                }
            }
        }
        // ---- residual + LayerNorm ----
#pragma unroll
        for (int e = 0; e < 6; e++) {
            int nid = nbase + w * 6 + e;
            int nc = nid < Nv ? nid : Nv - 1;
            float h0 = g_h[(size_t)nc * 64 + lane];
            float h1 = g_h[(size_t)nc * 64 + 32 + lane];
            float x0 = h0 + hadd2(o0[e]) + b2s[lane];
            float x1 = h1 + hadd2(o1[e]) + b2s[lane + 32];
            float s = x0 + x1, q = x0 * x0 + x1 * x1;
#pragma unroll
            for (int d = 16; d; d >>= 1) {
                s += __shfl_xor_sync(0xffffffffu, s, d);
                q += __shfl_xor_sync(0xffffffffu, q, d);
            }
            float mu = s * (1.0f / 64.0f);
            float var = q * (1.0f / 64.0f) - mu * mu;
            float inv = rsqrtf(var + 1e-6f);
            if (nid < Nv) {
                g_h[(size_t)nid * 64 + lane]      = (x0 - mu) * inv * lns[lane] + lnb[lane];
                g_h[(size_t)nid * 64 + 32 + lane] = (x1 - mu) * inv * lns[lane + 32] + lnb[lane + 32];
            }
        }
        __syncthreads();
    }
}

// ---------------------------------------------------------------------------
__global__ void decode_kernel(const float* __restrict__ dec_w,
                              const float* __restrict__ dec_b,
                              float* __restrict__ out, int Nv) {
    int gwarp = (blockIdx.x * blockDim.x + threadIdx.x) >> 5;
    int lane = threadIdx.x & 31;
    int nWarps = (gridDim.x * blockDim.x) >> 5;
    for (int n = gwarp; n < Nv; n += nWarps) {
        float h0 = g_h[n * 64 + lane];
        float h1 = g_h[n * 64 + 32 + lane];
        float p[7];
#pragma unroll
        for (int k = 0; k < 7; k++)
            p[k] = h0 * dec_w[lane * 7 + k] + h1 * dec_w[(lane + 32) * 7 + k];
#pragma unroll
        for (int k = 0; k < 7; k++)
#pragma unroll
            for (int d = 16; d; d >>= 1) p[k] += __shfl_xor_sync(0xffffffffu, p[k], d);
        if (lane < 7) out[n * 7 + lane] = p[lane] + dec_b[lane];
    }
}

// ---------------------------------------------------------------------------
extern "C" void kernel_launch(void* const* d_in, const int* in_sizes, int n_in,
                              void* d_out, int out_size) {
    const float* nodes   = (const float*)d_in[0];
    const int*   senders = (const int*)d_in[1];
    const int*   recvrs  = (const int*)d_in[2];
    const float* g       = (const float*)d_in[3];
    const float* embed_w = (const float*)d_in[4];
    const float* embed_b = (const float*)d_in[5];
    const float* ew1f    = (const float*)d_in[6];
    const float* ew1r    = (const float*)d_in[7];
    const float* eb1     = (const float*)d_in[8];
    const float* ew2     = (const float*)d_in[9];
    const float* eb2     = (const float*)d_in[10];
    const float* nw1     = (const float*)d_in[11];
    const float* nb1     = (const float*)d_in[12];
    const float* nw2     = (const float*)d_in[13];
    const float* nb2     = (const float*)d_in[14];
    const float* lnsc    = (const float*)d_in[15];
    const float* lnbi    = (const float*)d_in[16];
    const float* dec_w   = (const float*)d_in[17];
    const float* dec_b   = (const float*)d_in[18];
    float* out = (float*)d_out;

    int En = in_sizes[1];
    int Nv = in_sizes[0] / 7;

    size_t sm_pre = (size_t)(128 * 68 * 2 + 16 * 6 * 68) * 4;
    size_t sm_e0  = (size_t)(64 * 132 + 64 + 16 * 6 * 132) * 4;
    size_t sm_e1  = (size_t)(64 * 132 + 64 + 128 * 68 + 16 * 6 * 68 + 16 * 6 * 132) * 4;
    size_t sm_n   = (size_t)(128 * 132 + 64 * 132 + 64 + 64 + 64 + 96 * 132) * 4;

    cudaFuncSetAttribute(pre_kernel,
                         cudaFuncAttributeMaxDynamicSharedMemorySize, (int)sm_pre);
    cudaFuncSetAttribute(edge_kernel<false>,
                         cudaFuncAttributeMaxDynamicSharedMemorySize, (int)sm_e0);
    cudaFuncSetAttribute(edge_kernel<true>,
                         cudaFuncAttributeMaxDynamicSharedMemorySize, (int)sm_e1);
    cudaFuncSetAttribute(node_kernel,
                         cudaFuncAttributeMaxDynamicSharedMemorySize, (int)sm_n);

    const int GRID = 148;
    const int GRID_N = 131;

    embed_kernel<<<(Nv * 64 + 255) / 256, 256>>>(nodes, embed_w, embed_b, Nv);
    zero_recv_kernel<<<(Nv * 64 + 255) / 256, 256>>>(Nv * 64);  // once; node_kernel re-zeros

    for (int t = 0; t < 3; t++) {
        if (t == 0) {
            // w1f rows: [0:64)=s, [64:128)=r, [128:144)=g
            const_kernel<<<1, 128>>>(g, ew1f + 128 * 128, eb1, 16, 0);
            pre_kernel<<<GRID, 512, sm_pre>>>(ew1f, ew1f + 64 * 128, Nv);
            edge_kernel<false><<<GRID, 512, sm_e0>>>(
                senders, recvrs, nullptr, ew2, eb2, En, 1);
        } else {
            // w1rest[t-1] rows: [0:64)=e, [64:128)=s, [128:192)=r, [192:208)=g
            const float* base = ew1r + (size_t)(t - 1) * 208 * 128;
            const_kernel<<<1, 128>>>(g, base + 192 * 128, eb1 + t * 128, 16, 0);
            pre_kernel<<<GRID, 512, sm_pre>>>(base + 64 * 128, base + 128 * 128, Nv);
            edge_kernel<true><<<GRID, 512, sm_e1>>>(
                senders, recvrs, base,
                ew2 + (size_t)t * 128 * 64, eb2 + t * 64, En, (t == 2) ? 0 : 1);
        }
        // node: w1 rows [0:64)=h, [64:128)=recv, [128:144)=g (folded into g_cn)
        const float* nbase = nw1 + (size_t)t * 144 * 128;
        const_kernel<<<1, 128>>>(g, nbase + 128 * 128, nb1 + t * 128, 16, 1);
        node_kernel<<<GRID_N, 512, sm_n>>>(
            nbase, nw2 + (size_t)t * 128 * 64, nb2 + t * 64,
            lnsc + t * 64, lnbi + t * 64, Nv);
    }

    decode_kernel<<<208, 256>>>(dec_w, dec_b, out, Nv);
}

// round 15
// speedup vs baseline: 1.0909x; 1.0473x over previous
#include <cuda_runtime.h>
#include <math.h>

#define NN 50000
#define EE 800000

__device__ float g_h[NN * 64];
__device__ float g_e[EE * 64];
__device__ float g_recv[NN * 64];
__device__ float g_hs[NN * 128];   // per-node sender-term (+ b1 + g-term)
__device__ float g_hr[NN * 128];   // per-node receiver-term
__device__ float g_c[3 * 128];     // edge: b1 + g @ w1_g, per step
__device__ float g_cn[3 * 128];    // node: b1 + g @ w1_g, per step

typedef unsigned long long u64;

#define FMA2(d, a, b) asm("fma.rn.f32x2 %0, %1, %2, %0;" : "+l"(d) : "l"(a), "l"(b))

__device__ __forceinline__ u64 pack_lo(float v) {
    u64 d; float z = 0.0f;
    asm("mov.b64 %0, {%1, %2};" : "=l"(d) : "f"(v), "f"(z));
    return d;
}

__device__ __forceinline__ float hadd2(u64 v) {
    float lo, hi;
    asm("mov.b64 {%0, %1}, %2;" : "=f"(lo), "=f"(hi) : "l"(v));
    return lo + hi;
}

// jax.nn.gelu (approximate=True), tanh via exp (~1e-7 accurate)
__device__ __forceinline__ float gelu_t(float x) {
    float y = 0.7978845608028654f * (x + 0.044715f * x * x * x);
    float e = __expf(2.0f * y);
    float th = 1.0f - __fdividef(2.0f, e + 1.0f);
    return 0.5f * x * (1.0f + th);
}

// ---------------------------------------------------------------------------
__global__ void embed_kernel(const float* __restrict__ nodes,
                             const float* __restrict__ w,
                             const float* __restrict__ b, int Nv) {
    int idx = blockIdx.x * blockDim.x + threadIdx.x;
    if (idx >= Nv * 64) return;
    int n = idx >> 6, j = idx & 63;
    float a = b[j];
#pragma unroll
    for (int k = 0; k < 7; k++) a += nodes[n * 7 + k] * w[k * 64 + j];
    g_h[idx] = a;
}

__global__ void zero_recv_kernel(int n) {
    int i = blockIdx.x * blockDim.x + threadIdx.x;
    if (i < n) g_recv[i] = 0.0f;
}

// All six bias+global constants in one launch. Blocks 0-2: edge steps;
// blocks 3-5: node steps.
__global__ void const_all_kernel(const float* __restrict__ gvec,
                                 const float* __restrict__ ew1f,
                                 const float* __restrict__ ew1r,
                                 const float* __restrict__ eb1,
                                 const float* __restrict__ nw1,
                                 const float* __restrict__ nb1) {
    int b = blockIdx.x;
    int j = threadIdx.x;  // 128
    const float* w1g;
    const float* bias;
    float* dst;
    if (b < 3) {
        w1g = (b == 0) ? (ew1f + 128 * 128)
                       : (ew1r + (size_t)(b - 1) * 208 * 128 + 192 * 128);
        bias = eb1 + b * 128;
        dst = g_c + b * 128;
    } else {
        int t = b - 3;
        w1g = nw1 + (size_t)t * 144 * 128 + 128 * 128;
        bias = nb1 + t * 128;
        dst = g_cn + t * 128;
    }
    float a = bias[j];
    for (int k = 0; k < 16; k++) a += gvec[k] * w1g[k * 128 + j];
    dst[j] = a;
}

// ---------------------------------------------------------------------------
// Per-node precompute: hs = h @ w1s + c ; hr = h @ w1r.  w1s/w1r are [64,128].
// 512 thr, warp = 6 nodes, grid-stride by warp.  (R12 structure)
// ---------------------------------------------------------------------------
__global__ __launch_bounds__(512, 1) void pre_kernel(
    const float* __restrict__ w1s, const float* __restrict__ w1r,
    int Nv, int step) {
    constexpr int WP = 68, HB = 68;
    extern __shared__ float sm[];
    float* wst  = sm;               // 128*68 [j][k]
    float* wrt  = wst + 128 * WP;   // 128*68
    float* hbuf = wrt + 128 * WP;   // 16*6*68

    int tid = threadIdx.x;
    for (int i = tid; i < 64 * 128; i += 512) {
        int k = i >> 7, j = i & 127;
        wst[j * WP + k] = w1s[i];
        wrt[j * WP + k] = w1r[i];
    }
    __syncthreads();

    int w = tid >> 5, lane = tid & 31;
    float* hb = hbuf + w * 6 * HB;
    int gw = blockIdx.x * 16 + w, stride = gridDim.x * 16;
    int nTiles = (Nv + 5) / 6;

    for (int tile = gw; tile < nTiles; tile += stride) {
        int nbase = tile * 6;
        for (int i = lane; i < 96; i += 32) {
            int e = i >> 4, q = i & 15;
            int nid = nbase + e; if (nid >= Nv) nid = Nv - 1;
            ((float4*)(hb + e * HB))[q] = ((const float4*)g_h)[(size_t)nid * 16 + q];
        }
        __syncwarp();
        // ---- hs pass (init with c) ----
        u64 acc[4][6];
#pragma unroll
        for (int u = 0; u < 4; u++) {
            float c = g_c[step * 128 + 32 * u + lane];
#pragma unroll
            for (int e = 0; e < 6; e++) acc[u][e] = pack_lo(c);
        }
        {
            const float* wb = wst + lane * WP;
#pragma unroll 2
            for (int k4 = 0; k4 < 16; k4++) {
                ulonglong2 wf[4];
#pragma unroll
                for (int u = 0; u < 4; u++)
                    wf[u] = *(const ulonglong2*)(wb + u * 32 * WP + 4 * k4);
#pragma unroll
                for (int e = 0; e < 6; e++) {
                    ulonglong2 av = *(const ulonglong2*)(hb + e * HB + 4 * k4);
#pragma unroll
                    for (int u = 0; u < 4; u++) {
                        FMA2(acc[u][e], av.x, wf[u].x);
                        FMA2(acc[u][e], av.y, wf[u].y);
                    }
                }
            }
        }
#pragma unroll
        for (int e = 0; e < 6; e++) {
            int nid = nbase + e;
            if (nid < Nv)
#pragma unroll
                for (int u = 0; u < 4; u++)
                    g_hs[(size_t)nid * 128 + 32 * u + lane] = hadd2(acc[u][e]);
        }
        // ---- hr pass (init 0) ----
#pragma unroll
        for (int u = 0; u < 4; u++)
#pragma unroll
            for (int e = 0; e < 6; e++) acc[u][e] = 0ull;
        {
            const float* wb = wrt + lane * WP;
#pragma unroll 2
            for (int k4 = 0; k4 < 16; k4++) {
                ulonglong2 wf[4];
#pragma unroll
                for (int u = 0; u < 4; u++)
                    wf[u] = *(const ulonglong2*)(wb + u * 32 * WP + 4 * k4);
#pragma unroll
                for (int e = 0; e < 6; e++) {
                    ulonglong2 av = *(const ulonglong2*)(hb + e * HB + 4 * k4);
#pragma unroll
                    for (int u = 0; u < 4; u++) {
                        FMA2(acc[u][e], av.x, wf[u].x);
                        FMA2(acc[u][e], av.y, wf[u].y);
                    }
                }
            }
        }
#pragma unroll
        for (int e = 0; e < 6; e++) {
            int nid = nbase + e;
            if (nid < Nv)
#pragma unroll
                for (int u = 0; u < 4; u++)
                    g_hr[(size_t)nid * 128 + 32 * u + lane] = hadd2(acc[u][e]);
        }
        __syncwarp();
    }
}

// ---------------------------------------------------------------------------
// Edge MLP with factored layer 1: hidden = gelu(hs[s] + hr[r] + (e@w1e)).
// Warp-private tiles of 6 edges, grid-stride; NO in-loop CTA barriers.
// ---------------------------------------------------------------------------
template <bool HAS_E>
__global__ __launch_bounds__(512, 1) void edge_kernel(
    const int* __restrict__ senders, const int* __restrict__ receivers,
    const float* __restrict__ w1e, const float* __restrict__ w2,
    const float* __restrict__ b2, int En, int write_e) {
    constexpr int W1P = 68, EBP = 68, HP = 132, W2P = 132;
    extern __shared__ float sm[];
    float* w2t  = sm;                              // 64*132 [j][k] k<128
    float* b2s  = w2t + 64 * W2P;                  // 64
    float* w1t  = b2s + 64;                        // HAS_E: 128*68 [j][k] k<64
    float* ebuf = w1t + (HAS_E ? 128 * W1P : 0);   // HAS_E: 16*6*68
    float* hid  = ebuf + (HAS_E ? 16 * 6 * EBP : 0); // 16*6*132

    int tid = threadIdx.x;
    for (int i = tid; i < 128 * 64; i += 512) {
        int k = i >> 6, j = i & 63;
        w2t[j * W2P + k] = w2[i];
    }
    if (HAS_E)
        for (int i = tid; i < 64 * 128; i += 512) {
            int k = i >> 7, j = i & 127;
            w1t[j * W1P + k] = w1e[i];
        }
    if (tid < 64) b2s[tid] = b2[tid];
    __syncthreads();

    int w = tid >> 5, lane = tid & 31;
    float* eb = ebuf + w * 6 * EBP;
    float* hidw = hid + w * 6 * HP;
    int gw = blockIdx.x * 16 + w, stride = gridDim.x * 16;
    int nTiles = (En + 5) / 6;

    for (int tile = gw; tile < nTiles; tile += stride) {
        int ebase = tile * 6;
        int se[6], re[6];
#pragma unroll
        for (int e = 0; e < 6; e++) {
            int eid = ebase + e; if (eid >= En) eid = En - 1;
            se[e] = senders[eid];
            re[e] = receivers[eid];
        }
        if (HAS_E) {
            for (int i = lane; i < 96; i += 32) {
                int e = i >> 4, q = i & 15;
                int eid = ebase + e; if (eid >= En) eid = En - 1;
                ((float4*)(eb + e * EBP))[q] = ((const float4*)g_e)[(size_t)eid * 16 + q];
            }
            __syncwarp();
        }
        // ---- layer 1: init from hs/hr gathers, then optional e@w1e ----
        u64 acc[4][6];
#pragma unroll
        for (int u = 0; u < 4; u++) {
            int j = 32 * u + lane;
#pragma unroll
            for (int e = 0; e < 6; e++) {
                float v = g_hs[(size_t)se[e] * 128 + j] + g_hr[(size_t)re[e] * 128 + j];
                acc[u][e] = pack_lo(v);
            }
        }
        if (HAS_E) {
            const float* wb = w1t + lane * W1P;
#pragma unroll 2
            for (int k4 = 0; k4 < 16; k4++) {
                ulonglong2 wf[4];
#pragma unroll
                for (int u = 0; u < 4; u++)
                    wf[u] = *(const ulonglong2*)(wb + u * 32 * W1P + 4 * k4);
#pragma unroll
                for (int e = 0; e < 6; e++) {
                    ulonglong2 av = *(const ulonglong2*)(eb + e * EBP + 4 * k4);
#pragma unroll
                    for (int u = 0; u < 4; u++) {
                        FMA2(acc[u][e], av.x, wf[u].x);
                        FMA2(acc[u][e], av.y, wf[u].y);
                    }
                }
            }
        }
        // ---- gelu into own-warp smem rows ----
#pragma unroll
        for (int e = 0; e < 6; e++)
#pragma unroll
            for (int u = 0; u < 4; u++) {
                int j = 32 * u + lane;
                hidw[e * HP + j] = gelu_t(hadd2(acc[u][e]));
            }
        __syncwarp();
        // ---- layer 2 ----
        u64 o0[6], o1[6];
#pragma unroll
        for (int e = 0; e < 6; e++) { o0[e] = 0ull; o1[e] = 0ull; }
        {
            const float* wa = w2t + lane * W2P;
            const float* wbp = w2t + (lane + 32) * W2P;
#pragma unroll 2
            for (int k4 = 0; k4 < 32; k4++) {
                ulonglong2 va = *(const ulonglong2*)(wa + 4 * k4);
                ulonglong2 vb = *(const ulonglong2*)(wbp + 4 * k4);
#pragma unroll
                for (int e = 0; e < 6; e++) {
                    ulonglong2 av = *(const ulonglong2*)(hidw + e * HP + 4 * k4);
                    FMA2(o0[e], av.x, va.x);
                    FMA2(o0[e], av.y, va.y);
                    FMA2(o1[e], av.x, vb.x);
                    FMA2(o1[e], av.y, vb.y);
                }
            }
        }
        // ---- scatter ----
#pragma unroll
        for (int e = 0; e < 6; e++) {
            int eid = ebase + e;
            if (eid < En) {
                float u0 = hadd2(o0[e]) + b2s[lane];
                float u1 = hadd2(o1[e]) + b2s[lane + 32];
                if (write_e) {
                    g_e[(size_t)eid * 64 + lane] = u0;
                    g_e[(size_t)eid * 64 + 32 + lane] = u1;
                }
                atomicAdd(&g_recv[(size_t)re[e] * 64 + lane], u0);
                atomicAdd(&g_recv[(size_t)re[e] * 64 + 32 + lane], u1);
            }
        }
        __syncwarp();
    }
}

// ---------------------------------------------------------------------------
// Fused node MLP + residual + LayerNorm. g-term folded into g_cn (k=128).
// LAST step fuses the decoder: out = LN(x) @ dec_w + dec_b (skips g_h store).
// ---------------------------------------------------------------------------
template <bool LAST>
__global__ __launch_bounds__(512, 1) void node_kernel(
    const float* __restrict__ w1, const float* __restrict__ w2,
    const float* __restrict__ b2,
    const float* __restrict__ lnsc, const float* __restrict__ lnbi,
    const float* __restrict__ dec_w, const float* __restrict__ dec_b,
    float* __restrict__ out, int Nv, int step) {
    constexpr int INP = 132, W1P = 132, W2P = 132, MB = 96, NT = 512;
    extern __shared__ float sm[];
    float* w1t = sm;                  // 128*132 [j][k] k<128
    float* w2t = w1t + 128 * W1P;     // 64*132
    float* b2s = w2t + 64 * W2P;      // 64
    float* lns = b2s + 64;            // 64
    float* lnb = lns + 64;            // 64
    float* dws = lnb + 64;            // LAST: 64*7 dec_w + 7 dec_b (pad 456)
    float* inb = dws + (LAST ? 456 : 0);  // MB*132 ; rows double as hid

    int tid = threadIdx.x;
    for (int i = tid; i < 128 * 128; i += NT) {
        int k = i >> 7, j = i & 127;
        w1t[j * W1P + k] = w1[i];
    }
    for (int i = tid; i < 128 * 64; i += NT) {
        int k = i >> 6, j = i & 63;
        w2t[j * W2P + k] = w2[i];
    }
    if (tid < 64) b2s[tid] = b2[tid];
    else if (tid < 128) lns[tid - 64] = lnsc[tid - 64];
    else if (tid < 192) lnb[tid - 128] = lnbi[tid - 128];
    if (LAST) {
        for (int i = tid; i < 448; i += NT) dws[i] = dec_w[i];
        if (tid < 7) dws[448 + tid] = dec_b[tid];
    }
    __syncthreads();

    int w = tid >> 5, lane = tid & 31;
    float cn[4];
#pragma unroll
    for (int u = 0; u < 4; u++) cn[u] = g_cn[step * 128 + 32 * u + lane];

    int nIter = (Nv + MB - 1) / MB;
    for (int it = blockIdx.x; it < nIter; it += gridDim.x) {
        int nbase = it * MB;
        // ---- gather [h | recv] ----
        {
            const float4* hp = (const float4*)g_h;
            const float4* rp = (const float4*)g_recv;
            for (int c = tid; c < MB * 32; c += NT) {
                int m = c >> 5, q = c & 31;
                int nid = nbase + m; if (nid >= Nv) nid = Nv - 1;
                float4 v = (q < 16) ? hp[(size_t)nid * 16 + q]
                                    : rp[(size_t)nid * 16 + (q - 16)];
                ((float4*)(inb + m * INP))[q] = v;
            }
        }
        __syncthreads();
        // ---- layer 1 ----
        u64 acc[4][6];
#pragma unroll
        for (int u = 0; u < 4; u++)
#pragma unroll
            for (int e = 0; e < 6; e++) acc[u][e] = pack_lo(cn[u]);
        {
            const float* inw = inb + (w * 6) * INP;
            const float* wb = w1t + lane * W1P;
#pragma unroll 2
            for (int k4 = 0; k4 < 32; k4++) {
                ulonglong2 wf[4];
#pragma unroll
                for (int u = 0; u < 4; u++)
                    wf[u] = *(const ulonglong2*)(wb + u * 32 * W1P + 4 * k4);
#pragma unroll
                for (int e = 0; e < 6; e++) {
                    ulonglong2 av = *(const ulonglong2*)(inw + e * INP + 4 * k4);
#pragma unroll
                    for (int u = 0; u < 4; u++) {
                        FMA2(acc[u][e], av.x, wf[u].x);
                        FMA2(acc[u][e], av.y, wf[u].y);
                    }
                }
            }
        }
        // ---- gelu into own rows of inb ----
        {
            float* hidw = inb + (w * 6) * INP;
#pragma unroll
            for (int e = 0; e < 6; e++)
#pragma unroll
                for (int u = 0; u < 4; u++) {
                    int j = 32 * u + lane;
                    hidw[e * INP + j] = gelu_t(hadd2(acc[u][e]));
                }
        }
        __syncwarp();
        // ---- layer 2 ----
        u64 o0[6], o1[6];
#pragma unroll
        for (int e = 0; e < 6; e++) { o0[e] = 0ull; o1[e] = 0ull; }
        {
            const float* hw = inb + (w * 6) * INP;
            const float* wa = w2t + lane * W2P;
            const float* wbp = w2t + (lane + 32) * W2P;
#pragma unroll 2
            for (int k4 = 0; k4 < 32; k4++) {
                ulonglong2 va = *(const ulonglong2*)(wa + 4 * k4);
                ulonglong2 vb = *(const ulonglong2*)(wbp + 4 * k4);
#pragma unroll
                for (int e = 0; e < 6; e++) {
                    ulonglong2 av = *(const ulonglong2*)(hw + e * INP + 4 * k4);
                    FMA2(o0[e], av.x, va.x);
                    FMA2(o0[e], av.y, va.y);
                    FMA2(o1[e], av.x, vb.x);
                    FMA2(o1[e], av.y, vb.y);
                }
            }
        }
        // ---- residual + LayerNorm (+ fused decode on LAST) ----
#pragma unroll
        for (int e = 0; e < 6; e++) {
            int nid = nbase + w * 6 + e;
            int nc = nid < Nv ? nid : Nv - 1;
            float h0 = g_h[(size_t)nc * 64 + lane];
            float h1 = g_h[(size_t)nc * 64 + 32 + lane];
            float x0 = h0 + hadd2(o0[e]) + b2s[lane];
            float x1 = h1 + hadd2(o1[e]) + b2s[lane + 32];
            float s = x0 + x1, q = x0 * x0 + x1 * x1;
#pragma unroll
            for (int d = 16; d; d >>= 1) {
                s += __shfl_xor_sync(0xffffffffu, s, d);
                q += __shfl_xor_sync(0xffffffffu, q, d);
            }
            float mu = s * (1.0f / 64.0f);
            float var = q * (1.0f / 64.0f) - mu * mu;
            float inv = rsqrtf(var + 1e-6f);
            float y0 = (x0 - mu) * inv * lns[lane] + lnb[lane];
            float y1 = (x1 - mu) * inv * lns[lane + 32] + lnb[lane + 32];
            if (!LAST) {
                if (nid < Nv) {
                    g_h[(size_t)nid * 64 + lane] = y0;
                    g_h[(size_t)nid * 64 + 32 + lane] = y1;
                }
            } else {
                float p[7];
#pragma unroll
                for (int f = 0; f < 7; f++)
                    p[f] = y0 * dws[lane * 7 + f] + y1 * dws[(lane + 32) * 7 + f];
#pragma unroll
                for (int f = 0; f < 7; f++)
#pragma unroll
                    for (int d = 16; d; d >>= 1)
                        p[f] += __shfl_xor_sync(0xffffffffu, p[f], d);
                if (nid < Nv && lane < 7) {
                    float v = p[0];
                    if (lane == 1) v = p[1];
                    else if (lane == 2) v = p[2];
                    else if (lane == 3) v = p[3];
                    else if (lane == 4) v = p[4];
                    else if (lane == 5) v = p[5];
                    else if (lane == 6) v = p[6];
                    out[(size_t)nid * 7 + lane] = v + dws[448 + lane];
                }
            }
        }
        __syncthreads();
    }
}

// ---------------------------------------------------------------------------
extern "C" void kernel_launch(void* const* d_in, const int* in_sizes, int n_in,
                              void* d_out, int out_size) {
    const float* nodes   = (const float*)d_in[0];
    const int*   senders = (const int*)d_in[1];
    const int*   recvrs  = (const int*)d_in[2];
    const float* g       = (const float*)d_in[3];
    const float* embed_w = (const float*)d_in[4];
    const float* embed_b = (const float*)d_in[5];
    const float* ew1f    = (const float*)d_in[6];
    const float* ew1r    = (const float*)d_in[7];
    const float* eb1     = (const float*)d_in[8];
    const float* ew2     = (const float*)d_in[9];
    const float* eb2     = (const float*)d_in[10];
    const float* nw1     = (const float*)d_in[11];
    const float* nb1     = (const float*)d_in[12];
    const float* nw2     = (const float*)d_in[13];
    const float* nb2     = (const float*)d_in[14];
    const float* lnsc    = (const float*)d_in[15];
    const float* lnbi    = (const float*)d_in[16];
    const float* dec_w   = (const float*)d_in[17];
    const float* dec_b   = (const float*)d_in[18];
    float* out = (float*)d_out;

    int En = in_sizes[1];
    int Nv = in_sizes[0] / 7;

    size_t sm_pre = (size_t)(128 * 68 * 2 + 16 * 6 * 68) * 4;
    size_t sm_e0  = (size_t)(64 * 132 + 64 + 16 * 6 * 132) * 4;
    size_t sm_e1  = (size_t)(64 * 132 + 64 + 128 * 68 + 16 * 6 * 68 + 16 * 6 * 132) * 4;
    size_t sm_n   = (size_t)(128 * 132 + 64 * 132 + 64 + 64 + 64 + 96 * 132) * 4;
    size_t sm_nl  = sm_n + 456 * 4;

    cudaFuncSetAttribute(pre_kernel,
                         cudaFuncAttributeMaxDynamicSharedMemorySize, (int)sm_pre);
    cudaFuncSetAttribute(edge_kernel<false>,
                         cudaFuncAttributeMaxDynamicSharedMemorySize, (int)sm_e0);
    cudaFuncSetAttribute(edge_kernel<true>,
                         cudaFuncAttributeMaxDynamicSharedMemorySize, (int)sm_e1);
    cudaFuncSetAttribute(node_kernel<false>,
                         cudaFuncAttributeMaxDynamicSharedMemorySize, (int)sm_n);
    cudaFuncSetAttribute(node_kernel<true>,
                         cudaFuncAttributeMaxDynamicSharedMemorySize, (int)sm_nl);

    const int GRID = 148;
    const int GRID_N = 131;

    embed_kernel<<<(Nv * 64 + 255) / 256, 256>>>(nodes, embed_w, embed_b, Nv);
    const_all_kernel<<<6, 128>>>(g, ew1f, ew1r, eb1, nw1, nb1);

    for (int t = 0; t < 3; t++) {
        zero_recv_kernel<<<(Nv * 64 + 255) / 256, 256>>>(Nv * 64);
        if (t == 0) {
            // w1f rows: [0:64)=s, [64:128)=r, [128:144)=g
            pre_kernel<<<GRID, 512, sm_pre>>>(ew1f, ew1f + 64 * 128, Nv, 0);
            edge_kernel<false><<<GRID, 512, sm_e0>>>(
                senders, recvrs, nullptr, ew2, eb2, En, 1);
        } else {
            // w1rest[t-1] rows: [0:64)=e, [64:128)=s, [128:192)=r, [192:208)=g
            const float* base = ew1r + (size_t)(t - 1) * 208 * 128;
            pre_kernel<<<GRID, 512, sm_pre>>>(base + 64 * 128, base + 128 * 128, Nv, t);
            edge_kernel<true><<<GRID, 512, sm_e1>>>(
                senders, recvrs, base,
                ew2 + (size_t)t * 128 * 64, eb2 + t * 64, En, (t == 2) ? 0 : 1);
        }
        // node: w1 rows [0:64)=h, [64:128)=recv, [128:144)=g (folded into g_cn)
        const float* nbase = nw1 + (size_t)t * 144 * 128;
        if (t < 2) {
            node_kernel<false><<<GRID_N, 512, sm_n>>>(
                nbase, nw2 + (size_t)t * 128 * 64, nb2 + t * 64,
                lnsc + t * 64, lnbi + t * 64,
                nullptr, nullptr, nullptr, Nv, t);
        } else {
            node_kernel<true><<<GRID_N, 512, sm_nl>>>(
                nbase, nw2 + (size_t)t * 128 * 64, nb2 + t * 64,
                lnsc + t * 64, lnbi + t * 64,
                dec_w, dec_b, out, Nv, t);
        }
    }
}

// round 16
// speedup vs baseline: 1.2065x; 1.1060x over previous
#include <cuda_runtime.h>
#include <math.h>

#define NN 50000
#define EE 800000

__device__ float g_h[NN * 64];
__device__ float g_e[EE * 64];
__device__ float g_recv[NN * 64];
__device__ float g_recvh[NN * 128];  // aggregated hidden (t=2 path)
__device__ float g_deg[NN];          // in-degree per node
__device__ float g_hs[NN * 128];
__device__ float g_hr[NN * 128];
__device__ float g_c[3 * 128];
__device__ float g_cn[3 * 128];

typedef unsigned long long u64;

#define FMA2(d, a, b) asm("fma.rn.f32x2 %0, %1, %2, %0;" : "+l"(d) : "l"(a), "l"(b))

__device__ __forceinline__ u64 pack_lo(float v) {
    u64 d; float z = 0.0f;
    asm("mov.b64 %0, {%1, %2};" : "=l"(d) : "f"(v), "f"(z));
    return d;
}

__device__ __forceinline__ float hadd2(u64 v) {
    float lo, hi;
    asm("mov.b64 {%0, %1}, %2;" : "=f"(lo), "=f"(hi) : "l"(v));
    return lo + hi;
}

__device__ __forceinline__ float gelu_t(float x) {
    float y = 0.7978845608028654f * (x + 0.044715f * x * x * x);
    float e = __expf(2.0f * y);
    float th = 1.0f - __fdividef(2.0f, e + 1.0f);
    return 0.5f * x * (1.0f + th);
}

// ---------------------------------------------------------------------------
__global__ void embed_kernel(const float* __restrict__ nodes,
                             const float* __restrict__ w,
                             const float* __restrict__ b, int Nv) {
    int idx = blockIdx.x * blockDim.x + threadIdx.x;
    if (idx >= Nv * 64) return;
    int n = idx >> 6, j = idx & 63;
    float a = b[j];
#pragma unroll
    for (int k = 0; k < 7; k++) a += nodes[n * 7 + k] * w[k * 64 + j];
    g_h[idx] = a;
}

__global__ void zero_recv_kernel(int n) {
    int i = blockIdx.x * blockDim.x + threadIdx.x;
    if (i < n) g_recv[i] = 0.0f;
}

__global__ void zero_recvh_kernel(int n) {
    int i = blockIdx.x * blockDim.x + threadIdx.x;
    if (i < n) g_recvh[i] = 0.0f;
}

__global__ void zero_deg_kernel(int n) {
    int i = blockIdx.x * blockDim.x + threadIdx.x;
    if (i < n) g_deg[i] = 0.0f;
}

__global__ void deg_kernel(const int* __restrict__ receivers, int En) {
    int i = blockIdx.x * blockDim.x + threadIdx.x;
    if (i < En) atomicAdd(&g_deg[receivers[i]], 1.0f);
}

// All six bias+global constants in one launch.
__global__ void const_all_kernel(const float* __restrict__ gvec,
                                 const float* __restrict__ ew1f,
                                 const float* __restrict__ ew1r,
                                 const float* __restrict__ eb1,
                                 const float* __restrict__ nw1,
                                 const float* __restrict__ nb1) {
    int b = blockIdx.x;
    int j = threadIdx.x;
    const float* w1g;
    const float* bias;
    float* dst;
    if (b < 3) {
        w1g = (b == 0) ? (ew1f + 128 * 128)
                       : (ew1r + (size_t)(b - 1) * 208 * 128 + 192 * 128);
        bias = eb1 + b * 128;
        dst = g_c + b * 128;
    } else {
        int t = b - 3;
        w1g = nw1 + (size_t)t * 144 * 128 + 128 * 128;
        bias = nb1 + t * 128;
        dst = g_cn + t * 128;
    }
    float a = bias[j];
    for (int k = 0; k < 16; k++) a += gvec[k] * w1g[k * 128 + j];
    dst[j] = a;
}

// ---------------------------------------------------------------------------
// Per-node precompute (R12 structure).
// ---------------------------------------------------------------------------
__global__ __launch_bounds__(512, 1) void pre_kernel(
    const float* __restrict__ w1s, const float* __restrict__ w1r,
    int Nv, int step) {
    constexpr int WP = 68, HB = 68;
    extern __shared__ float sm[];
    float* wst  = sm;
    float* wrt  = wst + 128 * WP;
    float* hbuf = wrt + 128 * WP;

    int tid = threadIdx.x;
    for (int i = tid; i < 64 * 128; i += 512) {
        int k = i >> 7, j = i & 127;
        wst[j * WP + k] = w1s[i];
        wrt[j * WP + k] = w1r[i];
    }
    __syncthreads();

    int w = tid >> 5, lane = tid & 31;
    float* hb = hbuf + w * 6 * HB;
    int gw = blockIdx.x * 16 + w, stride = gridDim.x * 16;
    int nTiles = (Nv + 5) / 6;

    for (int tile = gw; tile < nTiles; tile += stride) {
        int nbase = tile * 6;
        for (int i = lane; i < 96; i += 32) {
            int e = i >> 4, q = i & 15;
            int nid = nbase + e; if (nid >= Nv) nid = Nv - 1;
            ((float4*)(hb + e * HB))[q] = ((const float4*)g_h)[(size_t)nid * 16 + q];
        }
        __syncwarp();
        u64 acc[4][6];
#pragma unroll
        for (int u = 0; u < 4; u++) {
            float c = g_c[step * 128 + 32 * u + lane];
#pragma unroll
            for (int e = 0; e < 6; e++) acc[u][e] = pack_lo(c);
        }
        {
            const float* wb = wst + lane * WP;
#pragma unroll 2
            for (int k4 = 0; k4 < 16; k4++) {
                ulonglong2 wf[4];
#pragma unroll
                for (int u = 0; u < 4; u++)
                    wf[u] = *(const ulonglong2*)(wb + u * 32 * WP + 4 * k4);
#pragma unroll
                for (int e = 0; e < 6; e++) {
                    ulonglong2 av = *(const ulonglong2*)(hb + e * HB + 4 * k4);
#pragma unroll
                    for (int u = 0; u < 4; u++) {
                        FMA2(acc[u][e], av.x, wf[u].x);
                        FMA2(acc[u][e], av.y, wf[u].y);
                    }
                }
            }
        }
#pragma unroll
        for (int e = 0; e < 6; e++) {
            int nid = nbase + e;
            if (nid < Nv)
#pragma unroll
                for (int u = 0; u < 4; u++)
                    g_hs[(size_t)nid * 128 + 32 * u + lane] = hadd2(acc[u][e]);
        }
#pragma unroll
        for (int u = 0; u < 4; u++)
#pragma unroll
            for (int e = 0; e < 6; e++) acc[u][e] = 0ull;
        {
            const float* wb = wrt + lane * WP;
#pragma unroll 2
            for (int k4 = 0; k4 < 16; k4++) {
                ulonglong2 wf[4];
#pragma unroll
                for (int u = 0; u < 4; u++)
                    wf[u] = *(const ulonglong2*)(wb + u * 32 * WP + 4 * k4);
#pragma unroll
                for (int e = 0; e < 6; e++) {
                    ulonglong2 av = *(const ulonglong2*)(hb + e * HB + 4 * k4);
#pragma unroll
                    for (int u = 0; u < 4; u++) {
                        FMA2(acc[u][e], av.x, wf[u].x);
                        FMA2(acc[u][e], av.y, wf[u].y);
                    }
                }
            }
        }
#pragma unroll
        for (int e = 0; e < 6; e++) {
            int nid = nbase + e;
            if (nid < Nv)
#pragma unroll
                for (int u = 0; u < 4; u++)
                    g_hr[(size_t)nid * 128 + 32 * u + lane] = hadd2(acc[u][e]);
        }
        __syncwarp();
    }
}

// ---------------------------------------------------------------------------
// Edge MLP, full path (t=0,1): layer1 + gelu + layer2 + e-write + recv atomics.
// ---------------------------------------------------------------------------
template <bool HAS_E>
__global__ __launch_bounds__(512, 1) void edge_kernel(
    const int* __restrict__ senders, const int* __restrict__ receivers,
    const float* __restrict__ w1e, const float* __restrict__ w2,
    const float* __restrict__ b2, int En) {
    constexpr int W1P = 68, EBP = 68, HP = 132, W2P = 132;
    extern __shared__ float sm[];
    float* w2t  = sm;
    float* b2s  = w2t + 64 * W2P;
    float* w1t  = b2s + 64;
    float* ebuf = w1t + (HAS_E ? 128 * W1P : 0);
    float* hid  = ebuf + (HAS_E ? 16 * 6 * EBP : 0);

    int tid = threadIdx.x;
    for (int i = tid; i < 128 * 64; i += 512) {
        int k = i >> 6, j = i & 63;
        w2t[j * W2P + k] = w2[i];
    }
    if (HAS_E)
        for (int i = tid; i < 64 * 128; i += 512) {
            int k = i >> 7, j = i & 127;
            w1t[j * W1P + k] = w1e[i];
        }
    if (tid < 64) b2s[tid] = b2[tid];
    __syncthreads();

    int w = tid >> 5, lane = tid & 31;
    float* eb = ebuf + w * 6 * EBP;
    float* hidw = hid + w * 6 * HP;
    int gw = blockIdx.x * 16 + w, stride = gridDim.x * 16;
    int nTiles = (En + 5) / 6;

    for (int tile = gw; tile < nTiles; tile += stride) {
        int ebase = tile * 6;
        int se[6], re[6];
#pragma unroll
        for (int e = 0; e < 6; e++) {
            int eid = ebase + e; if (eid >= En) eid = En - 1;
            se[e] = senders[eid];
            re[e] = receivers[eid];
        }
        if (HAS_E) {
            for (int i = lane; i < 96; i += 32) {
                int e = i >> 4, q = i & 15;
                int eid = ebase + e; if (eid >= En) eid = En - 1;
                ((float4*)(eb + e * EBP))[q] = ((const float4*)g_e)[(size_t)eid * 16 + q];
            }
            __syncwarp();
        }
        u64 acc[4][6];
#pragma unroll
        for (int u = 0; u < 4; u++) {
            int j = 32 * u + lane;
#pragma unroll
            for (int e = 0; e < 6; e++) {
                float v = g_hs[(size_t)se[e] * 128 + j] + g_hr[(size_t)re[e] * 128 + j];
                acc[u][e] = pack_lo(v);
            }
        }
        if (HAS_E) {
            const float* wb = w1t + lane * W1P;
#pragma unroll 2
            for (int k4 = 0; k4 < 16; k4++) {
                ulonglong2 wf[4];
#pragma unroll
                for (int u = 0; u < 4; u++)
                    wf[u] = *(const ulonglong2*)(wb + u * 32 * W1P + 4 * k4);
#pragma unroll
                for (int e = 0; e < 6; e++) {
                    ulonglong2 av = *(const ulonglong2*)(eb + e * EBP + 4 * k4);
#pragma unroll
                    for (int u = 0; u < 4; u++) {
                        FMA2(acc[u][e], av.x, wf[u].x);
                        FMA2(acc[u][e], av.y, wf[u].y);
                    }
                }
            }
        }
#pragma unroll
        for (int e = 0; e < 6; e++)
#pragma unroll
            for (int u = 0; u < 4; u++) {
                int j = 32 * u + lane;
                hidw[e * HP + j] = gelu_t(hadd2(acc[u][e]));
            }
        __syncwarp();
        u64 o0[6], o1[6];
#pragma unroll
        for (int e = 0; e < 6; e++) { o0[e] = 0ull; o1[e] = 0ull; }
        {
            const float* wa = w2t + lane * W2P;
            const float* wbp = w2t + (lane + 32) * W2P;
#pragma unroll 2
            for (int k4 = 0; k4 < 32; k4++) {
                ulonglong2 va = *(const ulonglong2*)(wa + 4 * k4);
                ulonglong2 vb = *(const ulonglong2*)(wbp + 4 * k4);
#pragma unroll
                for (int e = 0; e < 6; e++) {
                    ulonglong2 av = *(const ulonglong2*)(hidw + e * HP + 4 * k4);
                    FMA2(o0[e], av.x, va.x);
                    FMA2(o0[e], av.y, va.y);
                    FMA2(o1[e], av.x, vb.x);
                    FMA2(o1[e], av.y, vb.y);
                }
            }
        }
#pragma unroll
        for (int e = 0; e < 6; e++) {
            int eid = ebase + e;
            if (eid < En) {
                float u0 = hadd2(o0[e]) + b2s[lane];
                float u1 = hadd2(o1[e]) + b2s[lane + 32];
                g_e[(size_t)eid * 64 + lane] = u0;
                g_e[(size_t)eid * 64 + 32 + lane] = u1;
                atomicAdd(&g_recv[(size_t)re[e] * 64 + lane], u0);
                atomicAdd(&g_recv[(size_t)re[e] * 64 + 32 + lane], u1);
            }
        }
        __syncwarp();
    }
}

// ---------------------------------------------------------------------------
// Edge AGG path (t=2): layer1 + gelu, aggregate 128-wide hidden at receivers.
// No per-edge layer2, no e-write. recv computed later by combine_kernel.
// ---------------------------------------------------------------------------
__global__ __launch_bounds__(512, 1) void edge_agg_kernel(
    const int* __restrict__ senders, const int* __restrict__ receivers,
    const float* __restrict__ w1e, int En) {
    constexpr int W1P = 68, EBP = 68;
    extern __shared__ float sm[];
    float* w1t  = sm;                  // 128*68
    float* ebuf = w1t + 128 * W1P;     // 16*6*68

    int tid = threadIdx.x;
    for (int i = tid; i < 64 * 128; i += 512) {
        int k = i >> 7, j = i & 127;
        w1t[j * W1P + k] = w1e[i];
    }
    __syncthreads();

    int w = tid >> 5, lane = tid & 31;
    float* eb = ebuf + w * 6 * EBP;
    int gw = blockIdx.x * 16 + w, stride = gridDim.x * 16;
    int nTiles = (En + 5) / 6;

    for (int tile = gw; tile < nTiles; tile += stride) {
        int ebase = tile * 6;
        int se[6], re[6];
#pragma unroll
        for (int e = 0; e < 6; e++) {
            int eid = ebase + e; if (eid >= En) eid = En - 1;
            se[e] = senders[eid];
            re[e] = receivers[eid];
        }
        for (int i = lane; i < 96; i += 32) {
            int e = i >> 4, q = i & 15;
            int eid = ebase + e; if (eid >= En) eid = En - 1;
            ((float4*)(eb + e * EBP))[q] = ((const float4*)g_e)[(size_t)eid * 16 + q];
        }
        __syncwarp();
        u64 acc[4][6];
#pragma unroll
        for (int u = 0; u < 4; u++) {
            int j = 32 * u + lane;
#pragma unroll
            for (int e = 0; e < 6; e++) {
                float v = g_hs[(size_t)se[e] * 128 + j] + g_hr[(size_t)re[e] * 128 + j];
                acc[u][e] = pack_lo(v);
            }
        }
        {
            const float* wb = w1t + lane * W1P;
#pragma unroll 2
            for (int k4 = 0; k4 < 16; k4++) {
                ulonglong2 wf[4];
#pragma unroll
                for (int u = 0; u < 4; u++)
                    wf[u] = *(const ulonglong2*)(wb + u * 32 * W1P + 4 * k4);
#pragma unroll
                for (int e = 0; e < 6; e++) {
                    ulonglong2 av = *(const ulonglong2*)(eb + e * EBP + 4 * k4);
#pragma unroll
                    for (int u = 0; u < 4; u++) {
                        FMA2(acc[u][e], av.x, wf[u].x);
                        FMA2(acc[u][e], av.y, wf[u].y);
                    }
                }
            }
        }
        // gelu + aggregate into recvh (128-wide)
#pragma unroll
        for (int e = 0; e < 6; e++) {
            int eid = ebase + e;
            if (eid < En) {
                float* dst = g_recvh + (size_t)re[e] * 128;
#pragma unroll
                for (int u = 0; u < 4; u++) {
                    int j = 32 * u + lane;
                    atomicAdd(dst + j, gelu_t(hadd2(acc[u][e])));
                }
            }
        }
        __syncwarp();
    }
}

// ---------------------------------------------------------------------------
// combine: recv[n] = recvh[n] @ w2 + deg[n]*b2  (per-node 128->64 GEMM)
// ---------------------------------------------------------------------------
__global__ __launch_bounds__(512, 1) void combine_kernel(
    const float* __restrict__ w2, const float* __restrict__ b2, int Nv) {
    constexpr int W2P = 132, RB = 132;
    extern __shared__ float sm[];
    float* w2t  = sm;              // 64*132 [j][k] k<128
    float* b2s  = w2t + 64 * W2P;  // 64
    float* rbuf = b2s + 64;        // 16*6*132

    int tid = threadIdx.x;
    for (int i = tid; i < 128 * 64; i += 512) {
        int k = i >> 6, j = i & 63;
        w2t[j * W2P + k] = w2[i];
    }
    if (tid < 64) b2s[tid] = b2[tid];
    __syncthreads();

    int w = tid >> 5, lane = tid & 31;
    float* rb = rbuf + w * 6 * RB;
    int gw = blockIdx.x * 16 + w, stride = gridDim.x * 16;
    int nTiles = (Nv + 5) / 6;

    for (int tile = gw; tile < nTiles; tile += stride) {
        int nbase = tile * 6;
        for (int i = lane; i < 192; i += 32) {
            int e = i >> 5, q = i & 31;
            int nid = nbase + e; if (nid >= Nv) nid = Nv - 1;
            ((float4*)(rb + e * RB))[q] = ((const float4*)g_recvh)[(size_t)nid * 32 + q];
        }
        __syncwarp();
        u64 o0[6], o1[6];
#pragma unroll
        for (int e = 0; e < 6; e++) { o0[e] = 0ull; o1[e] = 0ull; }
        {
            const float* wa = w2t + lane * W2P;
            const float* wbp = w2t + (lane + 32) * W2P;
#pragma unroll 2
            for (int k4 = 0; k4 < 32; k4++) {
                ulonglong2 va = *(const ulonglong2*)(wa + 4 * k4);
                ulonglong2 vb = *(const ulonglong2*)(wbp + 4 * k4);
#pragma unroll
                for (int e = 0; e < 6; e++) {
                    ulonglong2 av = *(const ulonglong2*)(rb + e * RB + 4 * k4);
                    FMA2(o0[e], av.x, va.x);
                    FMA2(o0[e], av.y, va.y);
                    FMA2(o1[e], av.x, vb.x);
                    FMA2(o1[e], av.y, vb.y);
                }
            }
        }
#pragma unroll
        for (int e = 0; e < 6; e++) {
            int nid = nbase + e;
            if (nid < Nv) {
                float dg = g_deg[nid];
                g_recv[(size_t)nid * 64 + lane]      = hadd2(o0[e]) + dg * b2s[lane];
                g_recv[(size_t)nid * 64 + 32 + lane] = hadd2(o1[e]) + dg * b2s[lane + 32];
            }
        }
        __syncwarp();
    }
}

// ---------------------------------------------------------------------------
// Fused node MLP + residual + LayerNorm (+ fused decode on LAST).
// ---------------------------------------------------------------------------
template <bool LAST>
__global__ __launch_bounds__(512, 1) void node_kernel(
    const float* __restrict__ w1, const float* __restrict__ w2,
    const float* __restrict__ b2,
    const float* __restrict__ lnsc, const float* __restrict__ lnbi,
    const float* __restrict__ dec_w, const float* __restrict__ dec_b,
    float* __restrict__ out, int Nv, int step) {
    constexpr int INP = 132, W1P = 132, W2P = 132, MB = 96, NT = 512;
    extern __shared__ float sm[];
    float* w1t = sm;
    float* w2t = w1t + 128 * W1P;
    float* b2s = w2t + 64 * W2P;
    float* lns = b2s + 64;
    float* lnb = lns + 64;
    float* dws = lnb + 64;
    float* inb = dws + (LAST ? 456 : 0);

    int tid = threadIdx.x;
    for (int i = tid; i < 128 * 128; i += NT) {
        int k = i >> 7, j = i & 127;
        w1t[j * W1P + k] = w1[i];
    }
    for (int i = tid; i < 128 * 64; i += NT) {
        int k = i >> 6, j = i & 63;
        w2t[j * W2P + k] = w2[i];
    }
    if (tid < 64) b2s[tid] = b2[tid];
    else if (tid < 128) lns[tid - 64] = lnsc[tid - 64];
    else if (tid < 192) lnb[tid - 128] = lnbi[tid - 128];
    if (LAST) {
        for (int i = tid; i < 448; i += NT) dws[i] = dec_w[i];
        if (tid < 7) dws[448 + tid] = dec_b[tid];
    }
    __syncthreads();

    int w = tid >> 5, lane = tid & 31;
    float cn[4];
#pragma unroll
    for (int u = 0; u < 4; u++) cn[u] = g_cn[step * 128 + 32 * u + lane];

    int nIter = (Nv + MB - 1) / MB;
    for (int it = blockIdx.x; it < nIter; it += gridDim.x) {
        int nbase = it * MB;
        {
            const float4* hp = (const float4*)g_h;
            const float4* rp = (const float4*)g_recv;
            for (int c = tid; c < MB * 32; c += NT) {
                int m = c >> 5, q = c & 31;
                int nid = nbase + m; if (nid >= Nv) nid = Nv - 1;
                float4 v = (q < 16) ? hp[(size_t)nid * 16 + q]
                                    : rp[(size_t)nid * 16 + (q - 16)];
                ((float4*)(inb + m * INP))[q] = v;
            }
        }
        __syncthreads();
        u64 acc[4][6];
#pragma unroll
        for (int u = 0; u < 4; u++)
#pragma unroll
            for (int e = 0; e < 6; e++) acc[u][e] = pack_lo(cn[u]);
        {
            const float* inw = inb + (w * 6) * INP;
            const float* wb = w1t + lane * W1P;
#pragma unroll 2
            for (int k4 = 0; k4 < 32; k4++) {
                ulonglong2 wf[4];
#pragma unroll
                for (int u = 0; u < 4; u++)
                    wf[u] = *(const ulonglong2*)(wb + u * 32 * W1P + 4 * k4);
#pragma unroll
                for (int e = 0; e < 6; e++) {
                    ulonglong2 av = *(const ulonglong2*)(inw + e * INP + 4 * k4);
#pragma unroll
                    for (int u = 0; u < 4; u++) {
                        FMA2(acc[u][e], av.x, wf[u].x);
                        FMA2(acc[u][e], av.y, wf[u].y);
                    }
                }
            }
        }
        {
            float* hidw = inb + (w * 6) * INP;
#pragma unroll
            for (int e = 0; e < 6; e++)
#pragma unroll
                for (int u = 0; u < 4; u++) {
                    int j = 32 * u + lane;
                    hidw[e * INP + j] = gelu_t(hadd2(acc[u][e]));
                }
        }
        __syncwarp();
        u64 o0[6], o1[6];
#pragma unroll
        for (int e = 0; e < 6; e++) { o0[e] = 0ull; o1[e] = 0ull; }
        {
            const float* hw = inb + (w * 6) * INP;
            const float* wa = w2t + lane * W2P;
            const float* wbp = w2t + (lane + 32) * W2P;
#pragma unroll 2
            for (int k4 = 0; k4 < 32; k4++) {
                ulonglong2 va = *(const ulonglong2*)(wa + 4 * k4);
                ulonglong2 vb = *(const ulonglong2*)(wbp + 4 * k4);
#pragma unroll
                for (int e = 0; e < 6; e++) {
                    ulonglong2 av = *(const ulonglong2*)(hw + e * INP + 4 * k4);
                    FMA2(o0[e], av.x, va.x);
                    FMA2(o0[e], av.y, va.y);
                    FMA2(o1[e], av.x, vb.x);
                    FMA2(o1[e], av.y, vb.y);
                }
            }
        }
#pragma unroll
        for (int e = 0; e < 6; e++) {
            int nid = nbase + w * 6 + e;
            int nc = nid < Nv ? nid : Nv - 1;
            float h0 = g_h[(size_t)nc * 64 + lane];
            float h1 = g_h[(size_t)nc * 64 + 32 + lane];
            float x0 = h0 + hadd2(o0[e]) + b2s[lane];
            float x1 = h1 + hadd2(o1[e]) + b2s[lane + 32];
            float s = x0 + x1, q = x0 * x0 + x1 * x1;
#pragma unroll
            for (int d = 16; d; d >>= 1) {
                s += __shfl_xor_sync(0xffffffffu, s, d);
                q += __shfl_xor_sync(0xffffffffu, q, d);
            }
            float mu = s * (1.0f / 64.0f);
            float var = q * (1.0f / 64.0f) - mu * mu;
            float inv = rsqrtf(var + 1e-6f);
            float y0 = (x0 - mu) * inv * lns[lane] + lnb[lane];
            float y1 = (x1 - mu) * inv * lns[lane + 32] + lnb[lane + 32];
            if (!LAST) {
                if (nid < Nv) {
                    g_h[(size_t)nid * 64 + lane] = y0;
                    g_h[(size_t)nid * 64 + 32 + lane] = y1;
                }
            } else {
                float p[7];
#pragma unroll
                for (int f = 0; f < 7; f++)
                    p[f] = y0 * dws[lane * 7 + f] + y1 * dws[(lane + 32) * 7 + f];
#pragma unroll
                for (int f = 0; f < 7; f++)
#pragma unroll
                    for (int d = 16; d; d >>= 1)
                        p[f] += __shfl_xor_sync(0xffffffffu, p[f], d);
                if (nid < Nv && lane < 7) {
                    float v = p[0];
                    if (lane == 1) v = p[1];
                    else if (lane == 2) v = p[2];
                    else if (lane == 3) v = p[3];
                    else if (lane == 4) v = p[4];
                    else if (lane == 5) v = p[5];
                    else if (lane == 6) v = p[6];
                    out[(size_t)nid * 7 + lane] = v + dws[448 + lane];
                }
            }
        }
        __syncthreads();
    }
}

// ---------------------------------------------------------------------------
extern "C" void kernel_launch(void* const* d_in, const int* in_sizes, int n_in,
                              void* d_out, int out_size) {
    const float* nodes   = (const float*)d_in[0];
    const int*   senders = (const int*)d_in[1];
    const int*   recvrs  = (const int*)d_in[2];
    const float* g       = (const float*)d_in[3];
    const float* embed_w = (const float*)d_in[4];
    const float* embed_b = (const float*)d_in[5];
    const float* ew1f    = (const float*)d_in[6];
    const float* ew1r    = (const float*)d_in[7];
    const float* eb1     = (const float*)d_in[8];
    const float* ew2     = (const float*)d_in[9];
    const float* eb2     = (const float*)d_in[10];
    const float* nw1     = (const float*)d_in[11];
    const float* nb1     = (const float*)d_in[12];
    const float* nw2     = (const float*)d_in[13];
    const float* nb2     = (const float*)d_in[14];
    const float* lnsc    = (const float*)d_in[15];
    const float* lnbi    = (const float*)d_in[16];
    const float* dec_w   = (const float*)d_in[17];
    const float* dec_b   = (const float*)d_in[18];
    float* out = (float*)d_out;

    int En = in_sizes[1];
    int Nv = in_sizes[0] / 7;

    size_t sm_pre  = (size_t)(128 * 68 * 2 + 16 * 6 * 68) * 4;
    size_t sm_e0   = (size_t)(64 * 132 + 64 + 16 * 6 * 132) * 4;
    size_t sm_e1   = (size_t)(64 * 132 + 64 + 128 * 68 + 16 * 6 * 68 + 16 * 6 * 132) * 4;
    size_t sm_eagg = (size_t)(128 * 68 + 16 * 6 * 68) * 4;
    size_t sm_comb = (size_t)(64 * 132 + 64 + 16 * 6 * 132) * 4;
    size_t sm_n    = (size_t)(128 * 132 + 64 * 132 + 64 + 64 + 64 + 96 * 132) * 4;
    size_t sm_nl   = sm_n + 456 * 4;

    cudaFuncSetAttribute(pre_kernel,
                         cudaFuncAttributeMaxDynamicSharedMemorySize, (int)sm_pre);
    cudaFuncSetAttribute(edge_kernel<false>,
                         cudaFuncAttributeMaxDynamicSharedMemorySize, (int)sm_e0);
    cudaFuncSetAttribute(edge_kernel<true>,
                         cudaFuncAttributeMaxDynamicSharedMemorySize, (int)sm_e1);
    cudaFuncSetAttribute(edge_agg_kernel,
                         cudaFuncAttributeMaxDynamicSharedMemorySize, (int)sm_eagg);
    cudaFuncSetAttribute(combine_kernel,
                         cudaFuncAttributeMaxDynamicSharedMemorySize, (int)sm_comb);
    cudaFuncSetAttribute(node_kernel<false>,
                         cudaFuncAttributeMaxDynamicSharedMemorySize, (int)sm_n);
    cudaFuncSetAttribute(node_kernel<true>,
                         cudaFuncAttributeMaxDynamicSharedMemorySize, (int)sm_nl);

    const int GRID = 148;
    const int GRID_N = 131;

    embed_kernel<<<(Nv * 64 + 255) / 256, 256>>>(nodes, embed_w, embed_b, Nv);
    const_all_kernel<<<6, 128>>>(g, ew1f, ew1r, eb1, nw1, nb1);
    zero_deg_kernel<<<(Nv + 255) / 256, 256>>>(Nv);
    deg_kernel<<<(En + 255) / 256, 256>>>(recvrs, En);

    for (int t = 0; t < 3; t++) {
        if (t == 0) {
            zero_recv_kernel<<<(Nv * 64 + 255) / 256, 256>>>(Nv * 64);
            pre_kernel<<<GRID, 512, sm_pre>>>(ew1f, ew1f + 64 * 128, Nv, 0);
            edge_kernel<false><<<GRID, 512, sm_e0>>>(
                senders, recvrs, nullptr, ew2, eb2, En);
        } else if (t == 1) {
            zero_recv_kernel<<<(Nv * 64 + 255) / 256, 256>>>(Nv * 64);
            const float* base = ew1r;
            pre_kernel<<<GRID, 512, sm_pre>>>(base + 64 * 128, base + 128 * 128, Nv, 1);
            edge_kernel<true><<<GRID, 512, sm_e1>>>(
                senders, recvrs, base,
                ew2 + (size_t)1 * 128 * 64, eb2 + 1 * 64, En);
        } else {
            // t=2: aggregate-then-project (w2 linearity)
            zero_recvh_kernel<<<(Nv * 128 + 255) / 256, 256>>>(Nv * 128);
            const float* base = ew1r + (size_t)1 * 208 * 128;
            pre_kernel<<<GRID, 512, sm_pre>>>(base + 64 * 128, base + 128 * 128, Nv, 2);
            edge_agg_kernel<<<GRID, 512, sm_eagg>>>(senders, recvrs, base, En);
            combine_kernel<<<GRID, 512, sm_comb>>>(
                ew2 + (size_t)2 * 128 * 64, eb2 + 2 * 64, Nv);
        }
        const float* nbase = nw1 + (size_t)t * 144 * 128;
        if (t < 2) {
            node_kernel<false><<<GRID_N, 512, sm_n>>>(
                nbase, nw2 + (size_t)t * 128 * 64, nb2 + t * 64,
                lnsc + t * 64, lnbi + t * 64,
                nullptr, nullptr, nullptr, Nv, t);
        } else {
            node_kernel<true><<<GRID_N, 512, sm_nl>>>(
                nbase, nw2 + (size_t)t * 128 * 64, nb2 + t * 64,
                lnsc + t * 64, lnbi + t * 64,
                dec_w, dec_b, out, Nv, t);
        }
    }
}

// round 17
// speedup vs baseline: 1.2623x; 1.0463x over previous
#include <cuda_runtime.h>
#include <math.h>

#define NN 50000
#define EE 800000

__device__ float g_h[NN * 64];
__device__ float g_e[EE * 64];
__device__ float g_recv[NN * 64];
__device__ float g_recvh[NN * 128];  // aggregated hidden (t=2 path)
__device__ float g_deg[NN];          // in-degree per node
__device__ float g_hs[NN * 128];
__device__ float g_hr[NN * 128];
__device__ float g_c[3 * 128];
__device__ float g_cn[3 * 128];

typedef unsigned long long u64;

#define FMA2(d, a, b) asm("fma.rn.f32x2 %0, %1, %2, %0;" : "+l"(d) : "l"(a), "l"(b))

__device__ __forceinline__ u64 pack_lo(float v) {
    u64 d; float z = 0.0f;
    asm("mov.b64 %0, {%1, %2};" : "=l"(d) : "f"(v), "f"(z));
    return d;
}

__device__ __forceinline__ float hadd2(u64 v) {
    float lo, hi;
    asm("mov.b64 {%0, %1}, %2;" : "=f"(lo), "=f"(hi) : "l"(v));
    return lo + hi;
}

// jax.nn.gelu (approximate=True) with HW tanh (MUFU.TANH, rel err ~5e-4 on
// tanh output -> ~1e-4 on gelu; threshold is 1e-3).
__device__ __forceinline__ float gelu_t(float x) {
    float y = 0.7978845608028654f * (x + 0.044715f * x * x * x);
    float th;
    asm("tanh.approx.f32 %0, %1;" : "=f"(th) : "f"(y));
    return 0.5f * x * (1.0f + th);
}

// ---------------------------------------------------------------------------
__global__ void embed_kernel(const float* __restrict__ nodes,
                             const float* __restrict__ w,
                             const float* __restrict__ b, int Nv) {
    int idx = blockIdx.x * blockDim.x + threadIdx.x;
    if (idx >= Nv * 64) return;
    int n = idx >> 6, j = idx & 63;
    float a = b[j];
#pragma unroll
    for (int k = 0; k < 7; k++) a += nodes[n * 7 + k] * w[k * 64 + j];
    g_h[idx] = a;
}

__global__ void zero_recv_kernel(int n) {
    int i = blockIdx.x * blockDim.x + threadIdx.x;
    if (i < n) g_recv[i] = 0.0f;
}

__global__ void zero_recvh_kernel(int n) {
    int i = blockIdx.x * blockDim.x + threadIdx.x;
    if (i < n) g_recvh[i] = 0.0f;
}

__global__ void zero_deg_kernel(int n) {
    int i = blockIdx.x * blockDim.x + threadIdx.x;
    if (i < n) g_deg[i] = 0.0f;
}

__global__ void deg_kernel(const int* __restrict__ receivers, int En) {
    int i = blockIdx.x * blockDim.x + threadIdx.x;
    if (i < En) atomicAdd(&g_deg[receivers[i]], 1.0f);
}

__global__ void const_all_kernel(const float* __restrict__ gvec,
                                 const float* __restrict__ ew1f,
                                 const float* __restrict__ ew1r,
                                 const float* __restrict__ eb1,
                                 const float* __restrict__ nw1,
                                 const float* __restrict__ nb1) {
    int b = blockIdx.x;
    int j = threadIdx.x;
    const float* w1g;
    const float* bias;
    float* dst;
    if (b < 3) {
        w1g = (b == 0) ? (ew1f + 128 * 128)
                       : (ew1r + (size_t)(b - 1) * 208 * 128 + 192 * 128);
        bias = eb1 + b * 128;
        dst = g_c + b * 128;
    } else {
        int t = b - 3;
        w1g = nw1 + (size_t)t * 144 * 128 + 128 * 128;
        bias = nb1 + t * 128;
        dst = g_cn + t * 128;
    }
    float a = bias[j];
    for (int k = 0; k < 16; k++) a += gvec[k] * w1g[k * 128 + j];
    dst[j] = a;
}

// ---------------------------------------------------------------------------
__global__ __launch_bounds__(512, 1) void pre_kernel(
    const float* __restrict__ w1s, const float* __restrict__ w1r,
    int Nv, int step) {
    constexpr int WP = 68, HB = 68;
    extern __shared__ float sm[];
    float* wst  = sm;
    float* wrt  = wst + 128 * WP;
    float* hbuf = wrt + 128 * WP;

    int tid = threadIdx.x;
    for (int i = tid; i < 64 * 128; i += 512) {
        int k = i >> 7, j = i & 127;
        wst[j * WP + k] = w1s[i];
        wrt[j * WP + k] = w1r[i];
    }
    __syncthreads();

    int w = tid >> 5, lane = tid & 31;
    float* hb = hbuf + w * 6 * HB;
    int gw = blockIdx.x * 16 + w, stride = gridDim.x * 16;
    int nTiles = (Nv + 5) / 6;

    for (int tile = gw; tile < nTiles; tile += stride) {
        int nbase = tile * 6;
        for (int i = lane; i < 96; i += 32) {
            int e = i >> 4, q = i & 15;
            int nid = nbase + e; if (nid >= Nv) nid = Nv - 1;
            ((float4*)(hb + e * HB))[q] = ((const float4*)g_h)[(size_t)nid * 16 + q];
        }
        __syncwarp();
        u64 acc[4][6];
#pragma unroll
        for (int u = 0; u < 4; u++) {
            float c = g_c[step * 128 + 32 * u + lane];
#pragma unroll
            for (int e = 0; e < 6; e++) acc[u][e] = pack_lo(c);
        }
        {
            const float* wb = wst + lane * WP;
#pragma unroll 2
            for (int k4 = 0; k4 < 16; k4++) {
                ulonglong2 wf[4];
#pragma unroll
                for (int u = 0; u < 4; u++)
                    wf[u] = *(const ulonglong2*)(wb + u * 32 * WP + 4 * k4);
#pragma unroll
                for (int e = 0; e < 6; e++) {
                    ulonglong2 av = *(const ulonglong2*)(hb + e * HB + 4 * k4);
#pragma unroll
                    for (int u = 0; u < 4; u++) {
                        FMA2(acc[u][e], av.x, wf[u].x);
                        FMA2(acc[u][e], av.y, wf[u].y);
                    }
                }
            }
        }
#pragma unroll
        for (int e = 0; e < 6; e++) {
            int nid = nbase + e;
            if (nid < Nv)
#pragma unroll
                for (int u = 0; u < 4; u++)
                    g_hs[(size_t)nid * 128 + 32 * u + lane] = hadd2(acc[u][e]);
        }
#pragma unroll
        for (int u = 0; u < 4; u++)
#pragma unroll
            for (int e = 0; e < 6; e++) acc[u][e] = 0ull;
        {
            const float* wb = wrt + lane * WP;
#pragma unroll 2
            for (int k4 = 0; k4 < 16; k4++) {
                ulonglong2 wf[4];
#pragma unroll
                for (int u = 0; u < 4; u++)
                    wf[u] = *(const ulonglong2*)(wb + u * 32 * WP + 4 * k4);
#pragma unroll
                for (int e = 0; e < 6; e++) {
                    ulonglong2 av = *(const ulonglong2*)(hb + e * HB + 4 * k4);
#pragma unroll
                    for (int u = 0; u < 4; u++) {
                        FMA2(acc[u][e], av.x, wf[u].x);
                        FMA2(acc[u][e], av.y, wf[u].y);
                    }
                }
            }
        }
#pragma unroll
        for (int e = 0; e < 6; e++) {
            int nid = nbase + e;
            if (nid < Nv)
#pragma unroll
                for (int u = 0; u < 4; u++)
                    g_hr[(size_t)nid * 128 + 32 * u + lane] = hadd2(acc[u][e]);
        }
        __syncwarp();
    }
}

// ---------------------------------------------------------------------------
template <bool HAS_E>
__global__ __launch_bounds__(512, 1) void edge_kernel(
    const int* __restrict__ senders, const int* __restrict__ receivers,
    const float* __restrict__ w1e, const float* __restrict__ w2,
    const float* __restrict__ b2, int En) {
    constexpr int W1P = 68, EBP = 68, HP = 132, W2P = 132;
    extern __shared__ float sm[];
    float* w2t  = sm;
    float* b2s  = w2t + 64 * W2P;
    float* w1t  = b2s + 64;
    float* ebuf = w1t + (HAS_E ? 128 * W1P : 0);
    float* hid  = ebuf + (HAS_E ? 16 * 6 * EBP : 0);

    int tid = threadIdx.x;
    for (int i = tid; i < 128 * 64; i += 512) {
        int k = i >> 6, j = i & 63;
        w2t[j * W2P + k] = w2[i];
    }
    if (HAS_E)
        for (int i = tid; i < 64 * 128; i += 512) {
            int k = i >> 7, j = i & 127;
            w1t[j * W1P + k] = w1e[i];
        }
    if (tid < 64) b2s[tid] = b2[tid];
    __syncthreads();

    int w = tid >> 5, lane = tid & 31;
    float* eb = ebuf + w * 6 * EBP;
    float* hidw = hid + w * 6 * HP;
    int gw = blockIdx.x * 16 + w, stride = gridDim.x * 16;
    int nTiles = (En + 5) / 6;

    for (int tile = gw; tile < nTiles; tile += stride) {
        int ebase = tile * 6;
        int se[6], re[6];
#pragma unroll
        for (int e = 0; e < 6; e++) {
            int eid = ebase + e; if (eid >= En) eid = En - 1;
            se[e] = senders[eid];
            re[e] = receivers[eid];
        }
        if (HAS_E) {
            for (int i = lane; i < 96; i += 32) {
                int e = i >> 4, q = i & 15;
                int eid = ebase + e; if (eid >= En) eid = En - 1;
                ((float4*)(eb + e * EBP))[q] = ((const float4*)g_e)[(size_t)eid * 16 + q];
            }
            __syncwarp();
        }
        u64 acc[4][6];
#pragma unroll
        for (int u = 0; u < 4; u++) {
            int j = 32 * u + lane;
#pragma unroll
            for (int e = 0; e < 6; e++) {
                float v = g_hs[(size_t)se[e] * 128 + j] + g_hr[(size_t)re[e] * 128 + j];
                acc[u][e] = pack_lo(v);
            }
        }
        if (HAS_E) {
            const float* wb = w1t + lane * W1P;
#pragma unroll 2
            for (int k4 = 0; k4 < 16; k4++) {
                ulonglong2 wf[4];
#pragma unroll
                for (int u = 0; u < 4; u++)
                    wf[u] = *(const ulonglong2*)(wb + u * 32 * W1P + 4 * k4);
#pragma unroll
                for (int e = 0; e < 6; e++) {
                    ulonglong2 av = *(const ulonglong2*)(eb + e * EBP + 4 * k4);
#pragma unroll
                    for (int u = 0; u < 4; u++) {
                        FMA2(acc[u][e], av.x, wf[u].x);
                        FMA2(acc[u][e], av.y, wf[u].y);
                    }
                }
            }
        }
#pragma unroll
        for (int e = 0; e < 6; e++)
#pragma unroll
            for (int u = 0; u < 4; u++) {
                int j = 32 * u + lane;
                hidw[e * HP + j] = gelu_t(hadd2(acc[u][e]));
            }
        __syncwarp();
        u64 o0[6], o1[6];
#pragma unroll
        for (int e = 0; e < 6; e++) { o0[e] = 0ull; o1[e] = 0ull; }
        {
            const float* wa = w2t + lane * W2P;
            const float* wbp = w2t + (lane + 32) * W2P;
#pragma unroll 2
            for (int k4 = 0; k4 < 32; k4++) {
                ulonglong2 va = *(const ulonglong2*)(wa + 4 * k4);
                ulonglong2 vb = *(const ulonglong2*)(wbp + 4 * k4);
#pragma unroll
                for (int e = 0; e < 6; e++) {
                    ulonglong2 av = *(const ulonglong2*)(hidw + e * HP + 4 * k4);
                    FMA2(o0[e], av.x, va.x);
                    FMA2(o0[e], av.y, va.y);
                    FMA2(o1[e], av.x, vb.x);
                    FMA2(o1[e], av.y, vb.y);
                }
            }
        }
#pragma unroll
        for (int e = 0; e < 6; e++) {
            int eid = ebase + e;
            if (eid < En) {
                float u0 = hadd2(o0[e]) + b2s[lane];
                float u1 = hadd2(o1[e]) + b2s[lane + 32];
                g_e[(size_t)eid * 64 + lane] = u0;
                g_e[(size_t)eid * 64 + 32 + lane] = u1;
                atomicAdd(&g_recv[(size_t)re[e] * 64 + lane], u0);
                atomicAdd(&g_recv[(size_t)re[e] * 64 + 32 + lane], u1);
            }
        }
        __syncwarp();
    }
}

// ---------------------------------------------------------------------------
__global__ __launch_bounds__(512, 1) void edge_agg_kernel(
    const int* __restrict__ senders, const int* __restrict__ receivers,
    const float* __restrict__ w1e, int En) {
    constexpr int W1P = 68, EBP = 68;
    extern __shared__ float sm[];
    float* w1t  = sm;
    float* ebuf = w1t + 128 * W1P;

    int tid = threadIdx.x;
    for (int i = tid; i < 64 * 128; i += 512) {
        int k = i >> 7, j = i & 127;
        w1t[j * W1P + k] = w1e[i];
    }
    __syncthreads();

    int w = tid >> 5, lane = tid & 31;
    float* eb = ebuf + w * 6 * EBP;
    int gw = blockIdx.x * 16 + w, stride = gridDim.x * 16;
    int nTiles = (En + 5) / 6;

    for (int tile = gw; tile < nTiles; tile += stride) {
        int ebase = tile * 6;
        int se[6], re[6];
#pragma unroll
        for (int e = 0; e < 6; e++) {
            int eid = ebase + e; if (eid >= En) eid = En - 1;
            se[e] = senders[eid];
            re[e] = receivers[eid];
        }
        for (int i = lane; i < 96; i += 32) {
            int e = i >> 4, q = i & 15;
            int eid = ebase + e; if (eid >= En) eid = En - 1;
            ((float4*)(eb + e * EBP))[q] = ((const float4*)g_e)[(size_t)eid * 16 + q];
        }
        __syncwarp();
        u64 acc[4][6];
#pragma unroll
        for (int u = 0; u < 4; u++) {
            int j = 32 * u + lane;
#pragma unroll
            for (int e = 0; e < 6; e++) {
                float v = g_hs[(size_t)se[e] * 128 + j] + g_hr[(size_t)re[e] * 128 + j];
                acc[u][e] = pack_lo(v);
            }
        }
        {
            const float* wb = w1t + lane * W1P;
#pragma unroll 2
            for (int k4 = 0; k4 < 16; k4++) {
                ulonglong2 wf[4];
#pragma unroll
                for (int u = 0; u < 4; u++)
                    wf[u] = *(const ulonglong2*)(wb + u * 32 * W1P + 4 * k4);
#pragma unroll
                for (int e = 0; e < 6; e++) {
                    ulonglong2 av = *(const ulonglong2*)(eb + e * EBP + 4 * k4);
#pragma unroll
                    for (int u = 0; u < 4; u++) {
                        FMA2(acc[u][e], av.x, wf[u].x);
                        FMA2(acc[u][e], av.y, wf[u].y);
                    }
                }
            }
        }
#pragma unroll
        for (int e = 0; e < 6; e++) {
            int eid = ebase + e;
            if (eid < En) {
                float* dst = g_recvh + (size_t)re[e] * 128;
#pragma unroll
                for (int u = 0; u < 4; u++) {
                    int j = 32 * u + lane;
                    atomicAdd(dst + j, gelu_t(hadd2(acc[u][e])));
                }
            }
        }
        __syncwarp();
    }
}

// ---------------------------------------------------------------------------
__global__ __launch_bounds__(512, 1) void combine_kernel(
    const float* __restrict__ w2, const float* __restrict__ b2, int Nv) {
    constexpr int W2P = 132, RB = 132;
    extern __shared__ float sm[];
    float* w2t  = sm;
    float* b2s  = w2t + 64 * W2P;
    float* rbuf = b2s + 64;

    int tid = threadIdx.x;
    for (int i = tid; i < 128 * 64; i += 512) {
        int k = i >> 6, j = i & 63;
        w2t[j * W2P + k] = w2[i];
    }
    if (tid < 64) b2s[tid] = b2[tid];
    __syncthreads();

    int w = tid >> 5, lane = tid & 31;
    float* rb = rbuf + w * 6 * RB;
    int gw = blockIdx.x * 16 + w, stride = gridDim.x * 16;
    int nTiles = (Nv + 5) / 6;

    for (int tile = gw; tile < nTiles; tile += stride) {
        int nbase = tile * 6;
        for (int i = lane; i < 192; i += 32) {
            int e = i >> 5, q = i & 31;
            int nid = nbase + e; if (nid >= Nv) nid = Nv - 1;
            ((float4*)(rb + e * RB))[q] = ((const float4*)g_recvh)[(size_t)nid * 32 + q];
        }
        __syncwarp();
        u64 o0[6], o1[6];
#pragma unroll
        for (int e = 0; e < 6; e++) { o0[e] = 0ull; o1[e] = 0ull; }
        {
            const float* wa = w2t + lane * W2P;
            const float* wbp = w2t + (lane + 32) * W2P;
#pragma unroll 2
            for (int k4 = 0; k4 < 32; k4++) {
                ulonglong2 va = *(const ulonglong2*)(wa + 4 * k4);
                ulonglong2 vb = *(const ulonglong2*)(wbp + 4 * k4);
#pragma unroll
                for (int e = 0; e < 6; e++) {
                    ulonglong2 av = *(const ulonglong2*)(rb + e * RB + 4 * k4);
                    FMA2(o0[e], av.x, va.x);
                    FMA2(o0[e], av.y, va.y);
                    FMA2(o1[e], av.x, vb.x);
                    FMA2(o1[e], av.y, vb.y);
                }
            }
        }
#pragma unroll
        for (int e = 0; e < 6; e++) {
            int nid = nbase + e;
            if (nid < Nv) {
                float dg = g_deg[nid];
                g_recv[(size_t)nid * 64 + lane]      = hadd2(o0[e]) + dg * b2s[lane];
                g_recv[(size_t)nid * 64 + 32 + lane] = hadd2(o1[e]) + dg * b2s[lane + 32];
            }
        }
        __syncwarp();
    }
}

// ---------------------------------------------------------------------------
template <bool LAST>
__global__ __launch_bounds__(512, 1) void node_kernel(
    const float* __restrict__ w1, const float* __restrict__ w2,
    const float* __restrict__ b2,
    const float* __restrict__ lnsc, const float* __restrict__ lnbi,
    const float* __restrict__ dec_w, const float* __restrict__ dec_b,
    float* __restrict__ out, int Nv, int step) {
    constexpr int INP = 132, W1P = 132, W2P = 132, MB = 96, NT = 512;
    extern __shared__ float sm[];
    float* w1t = sm;
    float* w2t = w1t + 128 * W1P;
    float* b2s = w2t + 64 * W2P;
    float* lns = b2s + 64;
    float* lnb = lns + 64;
    float* dws = lnb + 64;
    float* inb = dws + (LAST ? 456 : 0);

    int tid = threadIdx.x;
    for (int i = tid; i < 128 * 128; i += NT) {
        int k = i >> 7, j = i & 127;
        w1t[j * W1P + k] = w1[i];
    }
    for (int i = tid; i < 128 * 64; i += NT) {
        int k = i >> 6, j = i & 63;
        w2t[j * W2P + k] = w2[i];
    }
    if (tid < 64) b2s[tid] = b2[tid];
    else if (tid < 128) lns[tid - 64] = lnsc[tid - 64];
    else if (tid < 192) lnb[tid - 128] = lnbi[tid - 128];
    if (LAST) {
        for (int i = tid; i < 448; i += NT) dws[i] = dec_w[i];
        if (tid < 7) dws[448 + tid] = dec_b[tid];
    }
    __syncthreads();

    int w = tid >> 5, lane = tid & 31;
    float cn[4];
#pragma unroll
    for (int u = 0; u < 4; u++) cn[u] = g_cn[step * 128 + 32 * u + lane];

    int nIter = (Nv + MB - 1) / MB;
    for (int it = blockIdx.x; it < nIter; it += gridDim.x) {
        int nbase = it * MB;
        {
            const float4* hp = (const float4*)g_h;
            const float4* rp = (const float4*)g_recv;
            for (int c = tid; c < MB * 32; c += NT) {
                int m = c >> 5, q = c & 31;
                int nid = nbase + m; if (nid >= Nv) nid = Nv - 1;
                float4 v = (q < 16) ? hp[(size_t)nid * 16 + q]
                                    : rp[(size_t)nid * 16 + (q - 16)];
                ((float4*)(inb + m * INP))[q] = v;
            }
        }
        __syncthreads();
        u64 acc[4][6];
#pragma unroll
        for (int u = 0; u < 4; u++)
#pragma unroll
            for (int e = 0; e < 6; e++) acc[u][e] = pack_lo(cn[u]);
        {
            const float* inw = inb + (w * 6) * INP;
            const float* wb = w1t + lane * W1P;
#pragma unroll 2
            for (int k4 = 0; k4 < 32; k4++) {
                ulonglong2 wf[4];
#pragma unroll
                for (int u = 0; u < 4; u++)
                    wf[u] = *(const ulonglong2*)(wb + u * 32 * W1P + 4 * k4);
#pragma unroll
                for (int e = 0; e < 6; e++) {
                    ulonglong2 av = *(const ulonglong2*)(inw + e * INP + 4 * k4);
#pragma unroll
                    for (int u = 0; u < 4; u++) {
                        FMA2(acc[u][e], av.x, wf[u].x);
                        FMA2(acc[u][e], av.y, wf[u].y);
                    }
                }
            }
        }
        {
            float* hidw = inb + (w * 6) * INP;
#pragma unroll
            for (int e = 0; e < 6; e++)
#pragma unroll
                for (int u = 0; u < 4; u++) {
                    int j = 32 * u + lane;
                    hidw[e * INP + j] = gelu_t(hadd2(acc[u][e]));
                }
        }
        __syncwarp();
        u64 o0[6], o1[6];
#pragma unroll
        for (int e = 0; e < 6; e++) { o0[e] = 0ull; o1[e] = 0ull; }
        {
            const float* hw = inb + (w * 6) * INP;
            const float* wa = w2t + lane * W2P;
            const float* wbp = w2t + (lane + 32) * W2P;
#pragma unroll 2
            for (int k4 = 0; k4 < 32; k4++) {
                ulonglong2 va = *(const ulonglong2*)(wa + 4 * k4);
                ulonglong2 vb = *(const ulonglong2*)(wbp + 4 * k4);
#pragma unroll
                for (int e = 0; e < 6; e++) {
                    ulonglong2 av = *(const ulonglong2*)(hw + e * INP + 4 * k4);
                    FMA2(o0[e], av.x, va.x);
                    FMA2(o0[e], av.y, va.y);
                    FMA2(o1[e], av.x, vb.x);
                    FMA2(o1[e], av.y, vb.y);
                }
            }
        }
#pragma unroll
        for (int e = 0; e < 6; e++) {
            int nid = nbase + w * 6 + e;
            int nc = nid < Nv ? nid : Nv - 1;
            float h0 = g_h[(size_t)nc * 64 + lane];
            float h1 = g_h[(size_t)nc * 64 + 32 + lane];
            float x0 = h0 + hadd2(o0[e]) + b2s[lane];
            float x1 = h1 + hadd2(o1[e]) + b2s[lane + 32];
            float s = x0 + x1, q = x0 * x0 + x1 * x1;
#pragma unroll
            for (int d = 16; d; d >>= 1) {
                s += __shfl_xor_sync(0xffffffffu, s, d);
                q += __shfl_xor_sync(0xffffffffu, q, d);
            }
            float mu = s * (1.0f / 64.0f);
            float var = q * (1.0f / 64.0f) - mu * mu;
            float inv = rsqrtf(var + 1e-6f);
            float y0 = (x0 - mu) * inv * lns[lane] + lnb[lane];
            float y1 = (x1 - mu) * inv * lns[lane + 32] + lnb[lane + 32];
            if (!LAST) {
                if (nid < Nv) {
                    g_h[(size_t)nid * 64 + lane] = y0;
                    g_h[(size_t)nid * 64 + 32 + lane] = y1;
                }
            } else {
                float p[7];
#pragma unroll
                for (int f = 0; f < 7; f++)
                    p[f] = y0 * dws[lane * 7 + f] + y1 * dws[(lane + 32) * 7 + f];
#pragma unroll
                for (int f = 0; f < 7; f++)
#pragma unroll
                    for (int d = 16; d; d >>= 1)
                        p[f] += __shfl_xor_sync(0xffffffffu, p[f], d);
                if (nid < Nv && lane < 7) {
                    float v = p[0];
                    if (lane == 1) v = p[1];
                    else if (lane == 2) v = p[2];
                    else if (lane == 3) v = p[3];
                    else if (lane == 4) v = p[4];
                    else if (lane == 5) v = p[5];
                    else if (lane == 6) v = p[6];
                    out[(size_t)nid * 7 + lane] = v + dws[448 + lane];
                }
            }
        }
        __syncthreads();
    }
}

// ---------------------------------------------------------------------------
extern "C" void kernel_launch(void* const* d_in, const int* in_sizes, int n_in,
                              void* d_out, int out_size) {
    const float* nodes   = (const float*)d_in[0];
    const int*   senders = (const int*)d_in[1];
    const int*   recvrs  = (const int*)d_in[2];
    const float* g       = (const float*)d_in[3];
    const float* embed_w = (const float*)d_in[4];
    const float* embed_b = (const float*)d_in[5];
    const float* ew1f    = (const float*)d_in[6];
    const float* ew1r    = (const float*)d_in[7];
    const float* eb1     = (const float*)d_in[8];
    const float* ew2     = (const float*)d_in[9];
    const float* eb2     = (const float*)d_in[10];
    const float* nw1     = (const float*)d_in[11];
    const float* nb1     = (const float*)d_in[12];
    const float* nw2     = (const float*)d_in[13];
    const float* nb2     = (const float*)d_in[14];
    const float* lnsc    = (const float*)d_in[15];
    const float* lnbi    = (const float*)d_in[16];
    const float* dec_w   = (const float*)d_in[17];
    const float* dec_b   = (const float*)d_in[18];
    float* out = (float*)d_out;

    int En = in_sizes[1];
    int Nv = in_sizes[0] / 7;

    size_t sm_pre  = (size_t)(128 * 68 * 2 + 16 * 6 * 68) * 4;
    size_t sm_e0   = (size_t)(64 * 132 + 64 + 16 * 6 * 132) * 4;
    size_t sm_e1   = (size_t)(64 * 132 + 64 + 128 * 68 + 16 * 6 * 68 + 16 * 6 * 132) * 4;
    size_t sm_eagg = (size_t)(128 * 68 + 16 * 6 * 68) * 4;
    size_t sm_comb = (size_t)(64 * 132 + 64 + 16 * 6 * 132) * 4;
    size_t sm_n    = (size_t)(128 * 132 + 64 * 132 + 64 + 64 + 64 + 96 * 132) * 4;
    size_t sm_nl   = sm_n + 456 * 4;

    cudaFuncSetAttribute(pre_kernel,
                         cudaFuncAttributeMaxDynamicSharedMemorySize, (int)sm_pre);
    cudaFuncSetAttribute(edge_kernel<false>,
                         cudaFuncAttributeMaxDynamicSharedMemorySize, (int)sm_e0);
    cudaFuncSetAttribute(edge_kernel<true>,
                         cudaFuncAttributeMaxDynamicSharedMemorySize, (int)sm_e1);
    cudaFuncSetAttribute(edge_agg_kernel,
                         cudaFuncAttributeMaxDynamicSharedMemorySize, (int)sm_eagg);
    cudaFuncSetAttribute(combine_kernel,
                         cudaFuncAttributeMaxDynamicSharedMemorySize, (int)sm_comb);
    cudaFuncSetAttribute(node_kernel<false>,
                         cudaFuncAttributeMaxDynamicSharedMemorySize, (int)sm_n);
    cudaFuncSetAttribute(node_kernel<true>,
                         cudaFuncAttributeMaxDynamicSharedMemorySize, (int)sm_nl);

    const int GRID = 148;
    const int GRID_N = 131;

    embed_kernel<<<(Nv * 64 + 255) / 256, 256>>>(nodes, embed_w, embed_b, Nv);
    const_all_kernel<<<6, 128>>>(g, ew1f, ew1r, eb1, nw1, nb1);
    zero_deg_kernel<<<(Nv + 255) / 256, 256>>>(Nv);
    deg_kernel<<<(En + 255) / 256, 256>>>(recvrs, En);

    for (int t = 0; t < 3; t++) {
        if (t == 0) {
            zero_recv_kernel<<<(Nv * 64 + 255) / 256, 256>>>(Nv * 64);
            pre_kernel<<<GRID, 512, sm_pre>>>(ew1f, ew1f + 64 * 128, Nv, 0);
            edge_kernel<false><<<GRID, 512, sm_e0>>>(
                senders, recvrs, nullptr, ew2, eb2, En);
        } else if (t == 1) {
            zero_recv_kernel<<<(Nv * 64 + 255) / 256, 256>>>(Nv * 64);
            const float* base = ew1r;
            pre_kernel<<<GRID, 512, sm_pre>>>(base + 64 * 128, base + 128 * 128, Nv, 1);
            edge_kernel<true><<<GRID, 512, sm_e1>>>(
                senders, recvrs, base,
                ew2 + (size_t)1 * 128 * 64, eb2 + 1 * 64, En);
        } else {
            zero_recvh_kernel<<<(Nv * 128 + 255) / 256, 256>>>(Nv * 128);
            const float* base = ew1r + (size_t)1 * 208 * 128;
            pre_kernel<<<GRID, 512, sm_pre>>>(base + 64 * 128, base + 128 * 128, Nv, 2);
            edge_agg_kernel<<<GRID, 512, sm_eagg>>>(senders, recvrs, base, En);
            combine_kernel<<<GRID, 512, sm_comb>>>(
                ew2 + (size_t)2 * 128 * 64, eb2 + 2 * 64, Nv);
        }
        const float* nbase = nw1 + (size_t)t * 144 * 128;
        if (t < 2) {
            node_kernel<false><<<GRID_N, 512, sm_n>>>(
                nbase, nw2 + (size_t)t * 128 * 64, nb2 + t * 64,
                lnsc + t * 64, lnbi + t * 64,
                nullptr, nullptr, nullptr, Nv, t);
        } else {
            node_kernel<true><<<GRID_N, 512, sm_nl>>>(
                nbase, nw2 + (size_t)t * 128 * 64, nb2 + t * 64,
                lnsc + t * 64, lnbi + t * 64,
                dec_w, dec_b, out, Nv, t);
        }
    }
}